// round 5
// baseline (speedup 1.0000x reference)
#include <cuda_runtime.h>
#include <cstdint>

// ---------------------------------------------------------------------------
// Problem: PhotonicNeuralNetwork — B=8192, D_in=1024, H=2048, D_out=2, fp32.
//   x = tanh(x)
//   for li in {0,1}:  x = tanh(x@W^T + b); x += normal(fold_in(key42,2li))*0.02
//                     thermal = 0.7*thermal + 0.3*(0.05*sum_b |x|)
//                     x += 0.05*(thermal @ K)   (K[i,j]=1/(i-j)^2)
//                     x += (x*cos(0.03*normal(fold_in(key42,2li+1))) - x)*0.03
//   out = x @ Wout^T + bout
// All JAX randomness reproduced bit-exactly (threefry partitionable mode).
// ---------------------------------------------------------------------------

#define BATCH 8192
#define HDIM  2048

// Scratch (module-static device globals; no runtime allocation).
__device__ __align__(16) float g_bufA[BATCH * HDIM];
__device__ __align__(16) float g_bufB[BATCH * HDIM];
__device__ __align__(16) float g_cs[HDIM];
__device__ __align__(16) float g_thermal[HDIM];
__device__ __align__(16) float g_tn[HDIM];

// ---------------------------------------------------------------------------
// Threefry-2x32, exact JAX round/key schedule.
// ---------------------------------------------------------------------------
__host__ __device__ __forceinline__ uint32_t rotl32(uint32_t x, uint32_t r) {
#if defined(__CUDA_ARCH__)
  return __funnelshift_l(x, x, r);
#else
  return (x << r) | (x >> (32u - r));
#endif
}

__host__ __device__ __forceinline__ void threefry2x32(
    uint32_t k0, uint32_t k1, uint32_t x0, uint32_t x1,
    uint32_t& o0, uint32_t& o1) {
  uint32_t ks2 = 0x1BD11BDAu ^ k0 ^ k1;
  x0 += k0; x1 += k1;
#define TF_ROUND(r) { x0 += x1; x1 = rotl32(x1, r); x1 ^= x0; }
  TF_ROUND(13u) TF_ROUND(15u) TF_ROUND(26u) TF_ROUND(6u)
  x0 += k1;  x1 += ks2 + 1u;
  TF_ROUND(17u) TF_ROUND(29u) TF_ROUND(16u) TF_ROUND(24u)
  x0 += ks2; x1 += k0 + 2u;
  TF_ROUND(13u) TF_ROUND(15u) TF_ROUND(26u) TF_ROUND(6u)
  x0 += k0;  x1 += k1 + 3u;
  TF_ROUND(17u) TF_ROUND(29u) TF_ROUND(16u) TF_ROUND(24u)
  x0 += k1;  x1 += ks2 + 4u;
  TF_ROUND(13u) TF_ROUND(15u) TF_ROUND(26u) TF_ROUND(6u)
  x0 += ks2; x1 += k0 + 5u;
#undef TF_ROUND
  o0 = x0; o1 = x1;
}

// XLA ErfInv (Giles), f32.
__device__ __forceinline__ float xla_erfinv(float x) {
  float w = -log1pf(-x * x);
  float p;
  if (w < 5.0f) {
    w -= 2.5f;
    p = 2.81022636e-08f;
    p = fmaf(p, w, 3.43273939e-07f);
    p = fmaf(p, w, -3.5233877e-06f);
    p = fmaf(p, w, -4.39150654e-06f);
    p = fmaf(p, w, 0.00021858087f);
    p = fmaf(p, w, -0.00125372503f);
    p = fmaf(p, w, -0.00417768164f);
    p = fmaf(p, w, 0.246640727f);
    p = fmaf(p, w, 1.50140941f);
  } else {
    w = sqrtf(w) - 3.0f;
    p = -0.000200214257f;
    p = fmaf(p, w, 0.000100950558f);
    p = fmaf(p, w, 0.00134934322f);
    p = fmaf(p, w, -0.00367342844f);
    p = fmaf(p, w, 0.00573950773f);
    p = fmaf(p, w, -0.0076224613f);
    p = fmaf(p, w, 0.00943887047f);
    p = fmaf(p, w, 1.00167406f);
    p = fmaf(p, w, 2.83297682f);
  }
  return p * x;
}

// jax.random.normal(key, ...)[flat index idx], partitionable threefry bits.
__device__ __forceinline__ float jax_normal(uint32_t k0, uint32_t k1, uint32_t idx) {
  uint32_t o0, o1;
  threefry2x32(k0, k1, 0u, idx, o0, o1);
  uint32_t bits = o0 ^ o1;
  float f = __uint_as_float((bits >> 9) | 0x3f800000u) - 1.0f;
  const float lo = __uint_as_float(0xBF7FFFFFu);  // nextafter(-1, 0)
  float u = fmaxf(fmaf(f, 2.0f, lo), lo);
  return 1.41421354f * xla_erfinv(u);   // 0x3FB504F3 = f32(sqrt(2))
}

// ---------------------------------------------------------------------------
// k0: elementwise tanh of the input -> g_bufA ([8192,1024] region)
// ---------------------------------------------------------------------------
__global__ void tanh_in_kernel(const float* __restrict__ x) {
  int gi = blockIdx.x * blockDim.x + threadIdx.x;
  float4 v = reinterpret_cast<const float4*>(x)[gi];
  v.x = tanhf(v.x); v.y = tanhf(v.y); v.z = tanhf(v.z); v.w = tanhf(v.w);
  reinterpret_cast<float4*>(g_bufA)[gi] = v;
}

// ---------------------------------------------------------------------------
// SGEMM: Y[m,n] = tanh( sum_k A[m,k]*W[n,k] + bias[n] ) + 0.02*normal(idx)
// 128x128 tile, BK=16, 256 threads, 8x8 per thread, double-buffered smem.
// ---------------------------------------------------------------------------
#define BM 128
#define BN 128
#define BK 16
#define BMP (BM + 4)
#define BNP (BN + 4)

__global__ void __launch_bounds__(256, 2)
gemm_tanh_noise_kernel(const float* __restrict__ A,
                       const float* __restrict__ W,
                       const float* __restrict__ bias,
                       float* __restrict__ Y,
                       int K, uint32_t nk0, uint32_t nk1) {
  __shared__ __align__(16) float As[2][BK][BMP];
  __shared__ __align__(16) float Ws[2][BK][BNP];

  const int tid = threadIdx.x;
  const int lr  = tid >> 2;          // 0..63
  const int lc  = (tid & 3) << 2;    // 0,4,8,12
  const int tx  = tid & 15;
  const int ty  = tid >> 4;
  const int bm  = blockIdx.y * BM;
  const int bn  = blockIdx.x * BN;

  const float* Ab = A + (size_t)(bm + lr) * K + lc;
  const float* Wb = W + (size_t)(bn + lr) * K + lc;
  const size_t rowK64 = (size_t)64 * K;

  float4 ra0, ra1, rw0, rw1;
  // prologue: tile 0
  ra0 = *reinterpret_cast<const float4*>(Ab);
  ra1 = *reinterpret_cast<const float4*>(Ab + rowK64);
  rw0 = *reinterpret_cast<const float4*>(Wb);
  rw1 = *reinterpret_cast<const float4*>(Wb + rowK64);
  As[0][lc + 0][lr] = ra0.x; As[0][lc + 1][lr] = ra0.y;
  As[0][lc + 2][lr] = ra0.z; As[0][lc + 3][lr] = ra0.w;
  As[0][lc + 0][lr + 64] = ra1.x; As[0][lc + 1][lr + 64] = ra1.y;
  As[0][lc + 2][lr + 64] = ra1.z; As[0][lc + 3][lr + 64] = ra1.w;
  Ws[0][lc + 0][lr] = rw0.x; Ws[0][lc + 1][lr] = rw0.y;
  Ws[0][lc + 2][lr] = rw0.z; Ws[0][lc + 3][lr] = rw0.w;
  Ws[0][lc + 0][lr + 64] = rw1.x; Ws[0][lc + 1][lr + 64] = rw1.y;
  Ws[0][lc + 2][lr + 64] = rw1.z; Ws[0][lc + 3][lr + 64] = rw1.w;
  __syncthreads();

  float acc[8][8];
#pragma unroll
  for (int i = 0; i < 8; ++i)
#pragma unroll
    for (int j = 0; j < 8; ++j) acc[i][j] = 0.0f;

  const int nk = K / BK;
  for (int kt = 0; kt < nk; ++kt) {
    const int cur = kt & 1;
    if (kt + 1 < nk) {
      const float* pa = Ab + (kt + 1) * BK;
      const float* pw = Wb + (kt + 1) * BK;
      ra0 = *reinterpret_cast<const float4*>(pa);
      ra1 = *reinterpret_cast<const float4*>(pa + rowK64);
      rw0 = *reinterpret_cast<const float4*>(pw);
      rw1 = *reinterpret_cast<const float4*>(pw + rowK64);
    }
#pragma unroll
    for (int k = 0; k < BK; ++k) {
      float a[8], w[8];
      *reinterpret_cast<float4*>(&a[0]) =
          *reinterpret_cast<const float4*>(&As[cur][k][ty * 4]);
      *reinterpret_cast<float4*>(&a[4]) =
          *reinterpret_cast<const float4*>(&As[cur][k][ty * 4 + 64]);
      *reinterpret_cast<float4*>(&w[0]) =
          *reinterpret_cast<const float4*>(&Ws[cur][k][tx * 4]);
      *reinterpret_cast<float4*>(&w[4]) =
          *reinterpret_cast<const float4*>(&Ws[cur][k][tx * 4 + 64]);
#pragma unroll
      for (int i = 0; i < 8; ++i)
#pragma unroll
        for (int j = 0; j < 8; ++j)
          acc[i][j] = fmaf(a[i], w[j], acc[i][j]);
    }
    if (kt + 1 < nk) {
      const int nxt = cur ^ 1;
      As[nxt][lc + 0][lr] = ra0.x; As[nxt][lc + 1][lr] = ra0.y;
      As[nxt][lc + 2][lr] = ra0.z; As[nxt][lc + 3][lr] = ra0.w;
      As[nxt][lc + 0][lr + 64] = ra1.x; As[nxt][lc + 1][lr + 64] = ra1.y;
      As[nxt][lc + 2][lr + 64] = ra1.z; As[nxt][lc + 3][lr + 64] = ra1.w;
      Ws[nxt][lc + 0][lr] = rw0.x; Ws[nxt][lc + 1][lr] = rw0.y;
      Ws[nxt][lc + 2][lr] = rw0.z; Ws[nxt][lc + 3][lr] = rw0.w;
      Ws[nxt][lc + 0][lr + 64] = rw1.x; Ws[nxt][lc + 1][lr + 64] = rw1.y;
      Ws[nxt][lc + 2][lr + 64] = rw1.z; Ws[nxt][lc + 3][lr + 64] = rw1.w;
    }
    __syncthreads();
  }

  // Epilogue: bias + tanh + exact JAX noise, vectorized stores.
  float bv[2][4];
#pragma unroll
  for (int jj = 0; jj < 2; ++jj)
#pragma unroll
    for (int j = 0; j < 4; ++j) bv[jj][j] = bias[bn + tx * 4 + jj * 64 + j];

#pragma unroll
  for (int ii = 0; ii < 2; ++ii) {
#pragma unroll
    for (int i = 0; i < 4; ++i) {
      const int m = bm + ty * 4 + ii * 64 + i;
      const uint32_t base = (uint32_t)m * 2048u;
#pragma unroll
      for (int jj = 0; jj < 2; ++jj) {
        const int n0 = bn + tx * 4 + jj * 64;
        float o[4];
#pragma unroll
        for (int j = 0; j < 4; ++j) {
          float pre = acc[ii * 4 + i][jj * 4 + j] + bv[jj][j];
          float y = tanhf(pre);
          float nz = jax_normal(nk0, nk1, base + (uint32_t)(n0 + j));
          o[j] = y + nz * 0.02f;
        }
        *reinterpret_cast<float4*>(Y + (size_t)m * 2048 + n0) =
            make_float4(o[0], o[1], o[2], o[3]);
      }
    }
  }
}

// ---------------------------------------------------------------------------
// Deterministic column abs-sum over batch: g_cs[h] = sum_b |g_bufB[b,h]|
// ---------------------------------------------------------------------------
__global__ void colsum_kernel() {
  const int lanec = threadIdx.x & 31;
  const int c = blockIdx.x * 32 + lanec;
  const int r = threadIdx.x >> 5;  // 0..7
  float s = 0.0f;
  const float* p = g_bufB + (size_t)r * 2048 + c;
  for (int row = r; row < BATCH; row += 8) {
    s += fabsf(*p);
    p += (size_t)8 * 2048;
  }
  __shared__ float sm[8][32];
  sm[r][lanec] = s;
  __syncthreads();
  if (r == 0) {
    float t = s;
#pragma unroll
    for (int q = 1; q < 8; ++q) t += sm[q][lanec];
    g_cs[c] = t;
  }
}

// thermal = (first ? 0 : 0.7*thermal) + 0.3*(cs*0.05)
__global__ void thermal_kernel(int first) {
  int i = blockIdx.x * blockDim.x + threadIdx.x;
  if (i < HDIM) {
    float lt = g_cs[i] * 0.05f;
    g_thermal[i] = first ? (0.3f * lt) : (0.7f * g_thermal[i] + 0.3f * lt);
  }
}

// g_tn[j] = 0.05 * sum_i thermal[i] * (i==j ? 0 : 1/(i-j)^2)
__global__ void thermal_matvec_kernel() {
  __shared__ float th[HDIM];
  __shared__ float rec[HDIM];
  const int tid = threadIdx.x;  // 128 threads
  for (int i = tid; i < HDIM; i += 128) {
    th[i] = g_thermal[i];
    float d = (float)i;
    rec[i] = (i == 0) ? 0.0f : (1.0f / (d * d));
  }
  __syncthreads();
  const int j = blockIdx.x * 128 + tid;
  float acc = 0.0f;
  for (int i = 0; i < HDIM; ++i) {
    int d = i - j; d = d < 0 ? -d : d;
    acc += th[i] * rec[d];
  }
  g_tn[j] = acc * 0.05f;
}

// ---------------------------------------------------------------------------
// finalize (layer 0): x = y + tn[h]; phase noise; write to g_bufA.
// ---------------------------------------------------------------------------
__global__ void finalize_kernel(uint32_t kp0, uint32_t kp1) {
  const int gi = blockIdx.x * blockDim.x + threadIdx.x;
  const int idx = gi << 2;
  float4 y = *reinterpret_cast<const float4*>(g_bufB + idx);
  float4 t = *reinterpret_cast<const float4*>(g_tn + (idx & 2047));
  float v[4] = {y.x, y.y, y.z, y.w};
  float tv[4] = {t.x, t.y, t.z, t.w};
#pragma unroll
  for (int c = 0; c < 4; ++c) {
    float xx = v[c] + tv[c];
    float ph = jax_normal(kp0, kp1, (uint32_t)(idx + c)) * 0.03f;
    xx = xx + (xx * cosf(ph) - xx) * 0.03f;
    v[c] = xx;
  }
  *reinterpret_cast<float4*>(g_bufA + idx) = make_float4(v[0], v[1], v[2], v[3]);
}

// ---------------------------------------------------------------------------
// finalize (layer 1) fused with the tiny output GEMM:
// out[b,d] = sum_h finalize(Y2[b,h]) * Wout[d,h] + bout[d]
// One block per batch row; deterministic shared-memory tree reduction.
// ---------------------------------------------------------------------------
__global__ void __launch_bounds__(256)
finalize_out_kernel(const float* __restrict__ Wout,
                    const float* __restrict__ bout,
                    float* __restrict__ out,
                    uint32_t kp0, uint32_t kp1) {
  const int b = blockIdx.x;
  const int tid = threadIdx.x;
  const float* row = g_bufB + (size_t)b * 2048;
  float a0 = 0.0f, a1 = 0.0f;
#pragma unroll
  for (int q = 0; q < 2; ++q) {
    const int h = (tid + q * 256) * 4;
    float4 y  = *reinterpret_cast<const float4*>(row + h);
    float4 t  = *reinterpret_cast<const float4*>(g_tn + h);
    float4 w0 = *reinterpret_cast<const float4*>(Wout + h);
    float4 w1 = *reinterpret_cast<const float4*>(Wout + 2048 + h);
    float yv[4] = {y.x, y.y, y.z, y.w};
    float tv[4] = {t.x, t.y, t.z, t.w};
    float w0v[4] = {w0.x, w0.y, w0.z, w0.w};
    float w1v[4] = {w1.x, w1.y, w1.z, w1.w};
#pragma unroll
    for (int c = 0; c < 4; ++c) {
      float xx = yv[c] + tv[c];
      float ph = jax_normal(kp0, kp1, (uint32_t)(b * 2048 + h + c)) * 0.03f;
      xx = xx + (xx * cosf(ph) - xx) * 0.03f;
      a0 += xx * w0v[c];
      a1 += xx * w1v[c];
    }
  }
  __shared__ float s0[256];
  __shared__ float s1[256];
  s0[tid] = a0; s1[tid] = a1;
  __syncthreads();
#pragma unroll
  for (int off = 128; off > 0; off >>= 1) {
    if (tid < off) { s0[tid] += s0[tid + off]; s1[tid] += s1[tid + off]; }
    __syncthreads();
  }
  if (tid == 0) {
    out[2 * b + 0] = s0[0] + bout[0];
    out[2 * b + 1] = s1[0] + bout[1];
  }
}

// ---------------------------------------------------------------------------
// Launch
// ---------------------------------------------------------------------------
extern "C" void kernel_launch(void* const* d_in, const int* in_sizes, int n_in,
                              void* d_out, int out_size) {
  (void)in_sizes; (void)n_in; (void)out_size;
  const float* x    = (const float*)d_in[0];
  const float* W1   = (const float*)d_in[1];
  const float* b1   = (const float*)d_in[2];
  const float* W2   = (const float*)d_in[3];
  const float* b2   = (const float*)d_in[4];
  const float* Wout = (const float*)d_in[5];
  const float* bout = (const float*)d_in[6];
  float* out = (float*)d_out;

  float *bufA = nullptr, *bufB = nullptr;
  cudaGetSymbolAddress((void**)&bufA, g_bufA);
  cudaGetSymbolAddress((void**)&bufB, g_bufB);

  // fold_in(key(42), d) for d = 0..3 : noise/phase keys per layer.
  uint32_t kno[2][2], kph[2][2];
  for (int li = 0; li < 2; ++li) {
    threefry2x32(0u, 42u, 0u, (uint32_t)(2 * li),     kno[li][0], kno[li][1]);
    threefry2x32(0u, 42u, 0u, (uint32_t)(2 * li + 1), kph[li][0], kph[li][1]);
  }

  // Layer 0
  tanh_in_kernel<<<8192, 256>>>(x);  // 8192*1024/4/256
  gemm_tanh_noise_kernel<<<dim3(16, 64), 256>>>(bufA, W1, b1, bufB, 1024,
                                                kno[0][0], kno[0][1]);
  colsum_kernel<<<64, 256>>>();
  thermal_kernel<<<2, 1024>>>(1);
  thermal_matvec_kernel<<<16, 128>>>();
  finalize_kernel<<<16384, 256>>>(kph[0][0], kph[0][1]);

  // Layer 1
  gemm_tanh_noise_kernel<<<dim3(16, 64), 256>>>(bufA, W2, b2, bufB, 2048,
                                                kno[1][0], kno[1][1]);
  colsum_kernel<<<64, 256>>>();
  thermal_kernel<<<2, 1024>>>(0);
  thermal_matvec_kernel<<<16, 128>>>();

  // Output projection fused with layer-1 finalize.
  finalize_out_kernel<<<8192, 256>>>(Wout, bout, out, kph[1][0], kph[1][1]);
}

// round 7
// speedup vs baseline: 1.6125x; 1.6125x over previous
#include <cuda_runtime.h>
#include <cuda_bf16.h>
#include <cstdint>

// ---------------------------------------------------------------------------
// PhotonicNeuralNetwork — B=8192, D_in=1024, H=2048, D_out=2, fp32.
// GEMMs on mma.sync bf16 (HMMA, base-sm_100-safe) with bf16x3 split precision.
// Exact JAX threefry/erfinv noise reproduction.
// ---------------------------------------------------------------------------

#define BATCH 8192
#define HDIM  2048

__device__ __align__(16) float         g_bufB[BATCH * HDIM];
__device__ __align__(16) __nv_bfloat16 g_Ahi[BATCH * HDIM];
__device__ __align__(16) __nv_bfloat16 g_Alo[BATCH * HDIM];
__device__ __align__(16) __nv_bfloat16 g_Whi[HDIM * HDIM];
__device__ __align__(16) __nv_bfloat16 g_Wlo[HDIM * HDIM];
__device__ __align__(16) float g_cs[HDIM];
__device__ __align__(16) float g_thermal[HDIM];
__device__ __align__(16) float g_tn[HDIM];

// ---------------------------------------------------------------------------
// Threefry-2x32, exact JAX round/key schedule.
// ---------------------------------------------------------------------------
__host__ __device__ __forceinline__ uint32_t rotl32(uint32_t x, uint32_t r) {
#if defined(__CUDA_ARCH__)
  return __funnelshift_l(x, x, r);
#else
  return (x << r) | (x >> (32u - r));
#endif
}

__host__ __device__ __forceinline__ void threefry2x32(
    uint32_t k0, uint32_t k1, uint32_t x0, uint32_t x1,
    uint32_t& o0, uint32_t& o1) {
  uint32_t ks2 = 0x1BD11BDAu ^ k0 ^ k1;
  x0 += k0; x1 += k1;
#define TF_ROUND(r) { x0 += x1; x1 = rotl32(x1, r); x1 ^= x0; }
  TF_ROUND(13u) TF_ROUND(15u) TF_ROUND(26u) TF_ROUND(6u)
  x0 += k1;  x1 += ks2 + 1u;
  TF_ROUND(17u) TF_ROUND(29u) TF_ROUND(16u) TF_ROUND(24u)
  x0 += ks2; x1 += k0 + 2u;
  TF_ROUND(13u) TF_ROUND(15u) TF_ROUND(26u) TF_ROUND(6u)
  x0 += k0;  x1 += k1 + 3u;
  TF_ROUND(17u) TF_ROUND(29u) TF_ROUND(16u) TF_ROUND(24u)
  x0 += k1;  x1 += ks2 + 4u;
  TF_ROUND(13u) TF_ROUND(15u) TF_ROUND(26u) TF_ROUND(6u)
  x0 += ks2; x1 += k0 + 5u;
#undef TF_ROUND
  o0 = x0; o1 = x1;
}

__device__ __forceinline__ float xla_erfinv(float x) {
  float w = -log1pf(-x * x);
  float p;
  if (w < 5.0f) {
    w -= 2.5f;
    p = 2.81022636e-08f;
    p = fmaf(p, w, 3.43273939e-07f);
    p = fmaf(p, w, -3.5233877e-06f);
    p = fmaf(p, w, -4.39150654e-06f);
    p = fmaf(p, w, 0.00021858087f);
    p = fmaf(p, w, -0.00125372503f);
    p = fmaf(p, w, -0.00417768164f);
    p = fmaf(p, w, 0.246640727f);
    p = fmaf(p, w, 1.50140941f);
  } else {
    w = sqrtf(w) - 3.0f;
    p = -0.000200214257f;
    p = fmaf(p, w, 0.000100950558f);
    p = fmaf(p, w, 0.00134934322f);
    p = fmaf(p, w, -0.00367342844f);
    p = fmaf(p, w, 0.00573950773f);
    p = fmaf(p, w, -0.0076224613f);
    p = fmaf(p, w, 0.00943887047f);
    p = fmaf(p, w, 1.00167406f);
    p = fmaf(p, w, 2.83297682f);
  }
  return p * x;
}

__device__ __forceinline__ float jax_normal(uint32_t k0, uint32_t k1, uint32_t idx) {
  uint32_t o0, o1;
  threefry2x32(k0, k1, 0u, idx, o0, o1);
  uint32_t bits = o0 ^ o1;
  float f = __uint_as_float((bits >> 9) | 0x3f800000u) - 1.0f;
  const float lo = __uint_as_float(0xBF7FFFFFu);
  float u = fmaxf(fmaf(f, 2.0f, lo), lo);
  return 1.41421354f * xla_erfinv(u);
}

// ---------------------------------------------------------------------------
// PTX helpers (all base-sm_100-safe: sm_80-era instructions)
// ---------------------------------------------------------------------------
__device__ __forceinline__ uint32_t smem_u32(const void* p) {
  uint32_t a;
  asm("{ .reg .u64 t; cvta.to.shared.u64 t, %1; cvt.u32.u64 %0, t; }"
      : "=r"(a) : "l"(p));
  return a;
}

__device__ __forceinline__ void cp16(uint32_t dst, const void* src) {
  asm volatile("cp.async.cg.shared.global [%0], [%1], 16;"
               :: "r"(dst), "l"(src) : "memory");
}

__device__ __forceinline__ void ldsm_x4(uint32_t* r, uint32_t addr) {
  asm volatile("ldmatrix.sync.aligned.m8n8.x4.shared.b16 {%0,%1,%2,%3}, [%4];"
               : "=r"(r[0]), "=r"(r[1]), "=r"(r[2]), "=r"(r[3]) : "r"(addr));
}
__device__ __forceinline__ void ldsm_x2(uint32_t* r, uint32_t addr) {
  asm volatile("ldmatrix.sync.aligned.m8n8.x2.shared.b16 {%0,%1}, [%2];"
               : "=r"(r[0]), "=r"(r[1]) : "r"(addr));
}

__device__ __forceinline__ void mma_bf16(float* d, const uint32_t* a,
                                         const uint32_t* b) {
  asm volatile(
      "mma.sync.aligned.m16n8k16.row.col.f32.bf16.bf16.f32 "
      "{%0,%1,%2,%3}, {%4,%5,%6,%7}, {%8,%9}, {%0,%1,%2,%3};"
      : "+f"(d[0]), "+f"(d[1]), "+f"(d[2]), "+f"(d[3])
      : "r"(a[0]), "r"(a[1]), "r"(a[2]), "r"(a[3]), "r"(b[0]), "r"(b[1]));
}

// ---------------------------------------------------------------------------
// bf16 hi/lo split converters
// ---------------------------------------------------------------------------
__device__ __forceinline__ void split_bf16(float v, __nv_bfloat16& h, __nv_bfloat16& l) {
  h = __float2bfloat16(v);
  l = __float2bfloat16(v - __bfloat162float(h));
}

__global__ void convert_w_kernel(const float* __restrict__ W, int n4) {
  int gi = blockIdx.x * blockDim.x + threadIdx.x;
  if (gi >= n4) return;
  float4 v = reinterpret_cast<const float4*>(W)[gi];
  float vv[4] = {v.x, v.y, v.z, v.w};
  __nv_bfloat16 h[4], l[4];
#pragma unroll
  for (int c = 0; c < 4; ++c) split_bf16(vv[c], h[c], l[c]);
  __nv_bfloat162* H = reinterpret_cast<__nv_bfloat162*>(g_Whi);
  __nv_bfloat162* L = reinterpret_cast<__nv_bfloat162*>(g_Wlo);
  H[2 * gi]     = __halves2bfloat162(h[0], h[1]);
  H[2 * gi + 1] = __halves2bfloat162(h[2], h[3]);
  L[2 * gi]     = __halves2bfloat162(l[0], l[1]);
  L[2 * gi + 1] = __halves2bfloat162(l[2], l[3]);
}

__global__ void tanh_in_kernel(const float* __restrict__ x) {
  int gi = blockIdx.x * blockDim.x + threadIdx.x;
  float4 v = reinterpret_cast<const float4*>(x)[gi];
  float vv[4] = {tanhf(v.x), tanhf(v.y), tanhf(v.z), tanhf(v.w)};
  __nv_bfloat16 h[4], l[4];
#pragma unroll
  for (int c = 0; c < 4; ++c) split_bf16(vv[c], h[c], l[c]);
  __nv_bfloat162* H = reinterpret_cast<__nv_bfloat162*>(g_Ahi);
  __nv_bfloat162* L = reinterpret_cast<__nv_bfloat162*>(g_Alo);
  H[2 * gi]     = __halves2bfloat162(h[0], h[1]);
  H[2 * gi + 1] = __halves2bfloat162(h[2], h[3]);
  L[2 * gi]     = __halves2bfloat162(l[0], l[1]);
  L[2 * gi + 1] = __halves2bfloat162(l[2], l[3]);
}

// ---------------------------------------------------------------------------
// HMMA GEMM: Y[m,n] = tanh(sum_k A[m,k]*W[n,k] + bias[n]) + 0.02*noise(m*2048+n)
// CTA 128x128, 8 warps (2x4), warp tile 64x32, BK=64 bf16, bf16x3.
// Smem rows are 128B, SW128-style XOR swizzle on 16B chunks.
// ---------------------------------------------------------------------------
#define TM 128
#define TN 128
#define CK 64
#define TILE_BYTES (128 * 128)                 // 16 KB per (matrix, hi/lo)
#define STAGE_BYTES (4 * TILE_BYTES)           // Ahi,Alo,Whi,Wlo = 64 KB
#define GEMM_DYN_SMEM (1024 + 2 * STAGE_BYTES) // 2 stages + align slack

__global__ void __launch_bounds__(256, 1)
gemm_bf16x3_kernel(const float* __restrict__ bias, int K,
                   uint32_t nk0, uint32_t nk1) {
  extern __shared__ char dynsmem[];
  __shared__ float sBias[TN];

  const int tid  = threadIdx.x;
  const int wid  = tid >> 5;
  const int lane = tid & 31;
  const int bn   = blockIdx.x * TN;
  const int bm   = blockIdx.y * TM;
  const int wr   = wid >> 2;   // 0..1 : warp row (64 rows each)
  const int wc   = wid & 3;    // 0..3 : warp col (32 cols each)

  const uint32_t smem = (smem_u32(dynsmem) + 1023u) & ~1023u;

  if (tid < TN) sBias[tid] = bias[bn + tid];

  // --- stage loader: thread-constant addressing -----------------------------
  const int lr = tid >> 3;                 // 0..31 row within 32-row pass
  const int lc = tid & 7;                  // 16B chunk 0..7
  const uint32_t sw = (uint32_t)((lc ^ (lr & 7)) << 4);
  const __nv_bfloat16* Ahi = g_Ahi;
  const __nv_bfloat16* Alo = g_Alo;
  const __nv_bfloat16* Whi = g_Whi;
  const __nv_bfloat16* Wlo = g_Wlo;

  auto load_stage = [&](int s, int ck) {
    const uint32_t base = smem + (uint32_t)s * STAGE_BYTES;
    const size_t kcol = (size_t)ck * CK + (size_t)lc * 8;
#pragma unroll
    for (int q = 0; q < 4; ++q) {
      const int r = lr + 32 * q;
      const uint32_t doff = (uint32_t)r * 128u + sw;
      const size_t aoff = (size_t)(bm + r) * K + kcol;
      const size_t woff = (size_t)(bn + r) * K + kcol;
      cp16(base + doff,                  Ahi + aoff);
      cp16(base + TILE_BYTES + doff,     Alo + aoff);
      cp16(base + 2 * TILE_BYTES + doff, Whi + woff);
      cp16(base + 3 * TILE_BYTES + doff, Wlo + woff);
    }
    asm volatile("cp.async.commit_group;" ::: "memory");
  };

  // --- per-lane ldmatrix address pieces -------------------------------------
  // A (x4): row = wr*64 + i*16 + (lane&15), chunk = 2*ks + (lane>>4)
  // B (x2): row = wc*32 + j*8  + (lane&7),  chunk = 2*ks + ((lane>>3)&1)
  const int aRow = wr * 64 + (lane & 15);
  const int aChk = lane >> 4;
  const int bRow = wc * 32 + (lane & 7);
  const int bChk = (lane >> 3) & 1;
  const uint32_t aSwz = (uint32_t)(lane & 7) << 4;   // (row&7)<<4 component
  const uint32_t bSwz = (uint32_t)(lane & 7) << 4;

  float acc[4][4][4];
#pragma unroll
  for (int i = 0; i < 4; ++i)
#pragma unroll
    for (int j = 0; j < 4; ++j)
#pragma unroll
      for (int t = 0; t < 4; ++t) acc[i][j][t] = 0.0f;

  const int nch = K / CK;
  load_stage(0, 0);

  for (int c = 0; c < nch; ++c) {
    const int s = c & 1;
    if (c + 1 < nch) {
      load_stage(s ^ 1, c + 1);
      asm volatile("cp.async.wait_group 1;" ::: "memory");
    } else {
      asm volatile("cp.async.wait_group 0;" ::: "memory");
    }
    __syncthreads();

    const uint32_t aHiB = smem + (uint32_t)s * STAGE_BYTES;
    const uint32_t aLoB = aHiB + TILE_BYTES;
    const uint32_t wHiB = aHiB + 2 * TILE_BYTES;
    const uint32_t wLoB = aHiB + 3 * TILE_BYTES;

#pragma unroll
    for (int ks = 0; ks < 4; ++ks) {
      uint32_t ahi[4][4], alo[4][4], whi[4][2], wlo[4][2];
#pragma unroll
      for (int i = 0; i < 4; ++i) {
        const uint32_t off =
            (uint32_t)(aRow + i * 16) * 128u +
            ((uint32_t)((2 * ks + aChk) << 4) ^ aSwz);
        ldsm_x4(ahi[i], aHiB + off);
        ldsm_x4(alo[i], aLoB + off);
      }
#pragma unroll
      for (int j = 0; j < 4; ++j) {
        const uint32_t off =
            (uint32_t)(bRow + j * 8) * 128u +
            ((uint32_t)((2 * ks + bChk) << 4) ^ bSwz);
        ldsm_x2(whi[j], wHiB + off);
        ldsm_x2(wlo[j], wLoB + off);
      }
#pragma unroll
      for (int i = 0; i < 4; ++i)
#pragma unroll
        for (int j = 0; j < 4; ++j) mma_bf16(acc[i][j], ahi[i], whi[j]);
#pragma unroll
      for (int i = 0; i < 4; ++i)
#pragma unroll
        for (int j = 0; j < 4; ++j) mma_bf16(acc[i][j], ahi[i], wlo[j]);
#pragma unroll
      for (int i = 0; i < 4; ++i)
#pragma unroll
        for (int j = 0; j < 4; ++j) mma_bf16(acc[i][j], alo[i], whi[j]);
    }
    __syncthreads();
  }

  // --- epilogue: bias + tanh + exact JAX noise -------------------------------
  const int r0 = bm + wr * 64 + (lane >> 2);
  const int c0l = wc * 32 + 2 * (lane & 3);
#pragma unroll
  for (int i = 0; i < 4; ++i) {
#pragma unroll
    for (int j = 0; j < 4; ++j) {
      const int cc = c0l + j * 8;
      const int cg = bn + cc;
#pragma unroll
      for (int hrow = 0; hrow < 2; ++hrow) {
        const int m = r0 + i * 16 + hrow * 8;
        const uint32_t nb = (uint32_t)m * 2048u + (uint32_t)cg;
        float v0 = acc[i][j][2 * hrow]     + sBias[cc];
        float v1 = acc[i][j][2 * hrow + 1] + sBias[cc + 1];
        v0 = tanhf(v0) + jax_normal(nk0, nk1, nb)     * 0.02f;
        v1 = tanhf(v1) + jax_normal(nk0, nk1, nb + 1) * 0.02f;
        *reinterpret_cast<float2*>(g_bufB + (size_t)m * HDIM + cg) =
            make_float2(v0, v1);
      }
    }
  }
}

// ---------------------------------------------------------------------------
// colsum / thermal / matvec
// ---------------------------------------------------------------------------
__global__ void colsum_kernel() {
  const int lanec = threadIdx.x & 31;
  const int c = blockIdx.x * 32 + lanec;
  const int r = threadIdx.x >> 5;
  float s = 0.0f;
  const float* p = g_bufB + (size_t)r * 2048 + c;
  for (int row = r; row < BATCH; row += 8) {
    s += fabsf(*p);
    p += (size_t)8 * 2048;
  }
  __shared__ float sm[8][32];
  sm[r][lanec] = s;
  __syncthreads();
  if (r == 0) {
    float t = s;
#pragma unroll
    for (int q = 1; q < 8; ++q) t += sm[q][lanec];
    g_cs[c] = t;
  }
}

__global__ void thermal_kernel(int first) {
  int i = blockIdx.x * blockDim.x + threadIdx.x;
  if (i < HDIM) {
    float lt = g_cs[i] * 0.05f;
    g_thermal[i] = first ? (0.3f * lt) : (0.7f * g_thermal[i] + 0.3f * lt);
  }
}

__global__ void thermal_matvec_kernel() {
  __shared__ float th[HDIM];
  __shared__ float rec[HDIM];
  const int tid = threadIdx.x;
  for (int i = tid; i < HDIM; i += 128) {
    th[i] = g_thermal[i];
    float d = (float)i;
    rec[i] = (i == 0) ? 0.0f : (1.0f / (d * d));
  }
  __syncthreads();
  const int j = blockIdx.x * 128 + tid;
  float acc = 0.0f;
  for (int i = 0; i < HDIM; ++i) {
    int d = i - j; d = d < 0 ? -d : d;
    acc += th[i] * rec[d];
  }
  g_tn[j] = acc * 0.05f;
}

// ---------------------------------------------------------------------------
// finalize (layer 0): x = y + tn; phase noise; split to bf16 hi/lo for GEMM2.
// ---------------------------------------------------------------------------
__global__ void finalize_kernel(uint32_t kp0, uint32_t kp1) {
  const int gi = blockIdx.x * blockDim.x + threadIdx.x;
  const int idx = gi << 2;
  float4 y = *reinterpret_cast<const float4*>(g_bufB + idx);
  float4 t = *reinterpret_cast<const float4*>(g_tn + (idx & 2047));
  float v[4] = {y.x, y.y, y.z, y.w};
  float tv[4] = {t.x, t.y, t.z, t.w};
  __nv_bfloat16 h[4], l[4];
#pragma unroll
  for (int c = 0; c < 4; ++c) {
    float xx = v[c] + tv[c];
    float ph = jax_normal(kp0, kp1, (uint32_t)(idx + c)) * 0.03f;
    xx = xx + (xx * cosf(ph) - xx) * 0.03f;
    split_bf16(xx, h[c], l[c]);
  }
  __nv_bfloat162* H = reinterpret_cast<__nv_bfloat162*>(g_Ahi);
  __nv_bfloat162* L = reinterpret_cast<__nv_bfloat162*>(g_Alo);
  H[2 * gi]     = __halves2bfloat162(h[0], h[1]);
  H[2 * gi + 1] = __halves2bfloat162(h[2], h[3]);
  L[2 * gi]     = __halves2bfloat162(l[0], l[1]);
  L[2 * gi + 1] = __halves2bfloat162(l[2], l[3]);
}

// ---------------------------------------------------------------------------
// finalize (layer 1) fused with output GEMM (D_out=2).
// ---------------------------------------------------------------------------
__global__ void __launch_bounds__(256)
finalize_out_kernel(const float* __restrict__ Wout,
                    const float* __restrict__ bout,
                    float* __restrict__ out,
                    uint32_t kp0, uint32_t kp1) {
  const int b = blockIdx.x;
  const int tid = threadIdx.x;
  const float* row = g_bufB + (size_t)b * 2048;
  float a0 = 0.0f, a1 = 0.0f;
#pragma unroll
  for (int q = 0; q < 2; ++q) {
    const int h = (tid + q * 256) * 4;
    float4 y  = *reinterpret_cast<const float4*>(row + h);
    float4 t  = *reinterpret_cast<const float4*>(g_tn + h);
    float4 w0 = *reinterpret_cast<const float4*>(Wout + h);
    float4 w1 = *reinterpret_cast<const float4*>(Wout + 2048 + h);
    float yv[4] = {y.x, y.y, y.z, y.w};
    float tv[4] = {t.x, t.y, t.z, t.w};
    float w0v[4] = {w0.x, w0.y, w0.z, w0.w};
    float w1v[4] = {w1.x, w1.y, w1.z, w1.w};
#pragma unroll
    for (int c = 0; c < 4; ++c) {
      float xx = yv[c] + tv[c];
      float ph = jax_normal(kp0, kp1, (uint32_t)(b * 2048 + h + c)) * 0.03f;
      xx = xx + (xx * cosf(ph) - xx) * 0.03f;
      a0 += xx * w0v[c];
      a1 += xx * w1v[c];
    }
  }
  __shared__ float s0[256];
  __shared__ float s1[256];
  s0[tid] = a0; s1[tid] = a1;
  __syncthreads();
#pragma unroll
  for (int off = 128; off > 0; off >>= 1) {
    if (tid < off) { s0[tid] += s0[tid + off]; s1[tid] += s1[tid + off]; }
    __syncthreads();
  }
  if (tid == 0) {
    out[2 * b + 0] = s0[0] + bout[0];
    out[2 * b + 1] = s1[0] + bout[1];
  }
}

// ---------------------------------------------------------------------------
// Launch
// ---------------------------------------------------------------------------
extern "C" void kernel_launch(void* const* d_in, const int* in_sizes, int n_in,
                              void* d_out, int out_size) {
  (void)in_sizes; (void)n_in; (void)out_size;
  const float* x    = (const float*)d_in[0];
  const float* W1   = (const float*)d_in[1];
  const float* b1   = (const float*)d_in[2];
  const float* W2   = (const float*)d_in[3];
  const float* b2   = (const float*)d_in[4];
  const float* Wout = (const float*)d_in[5];
  const float* bout = (const float*)d_in[6];
  float* out = (float*)d_out;

  cudaFuncSetAttribute(gemm_bf16x3_kernel,
                       cudaFuncAttributeMaxDynamicSharedMemorySize,
                       GEMM_DYN_SMEM);

  uint32_t kno[2][2], kph[2][2];
  for (int li = 0; li < 2; ++li) {
    threefry2x32(0u, 42u, 0u, (uint32_t)(2 * li),     kno[li][0], kno[li][1]);
    threefry2x32(0u, 42u, 0u, (uint32_t)(2 * li + 1), kph[li][0], kph[li][1]);
  }

  // Layer 0 (K = 1024)
  convert_w_kernel<<<2048, 256>>>(W1, 2048 * 1024 / 4);
  tanh_in_kernel<<<8192, 256>>>(x);
  gemm_bf16x3_kernel<<<dim3(HDIM / TN, BATCH / TM), 256, GEMM_DYN_SMEM>>>(
      b1, 1024, kno[0][0], kno[0][1]);
  colsum_kernel<<<64, 256>>>();
  thermal_kernel<<<2, 1024>>>(1);
  thermal_matvec_kernel<<<16, 128>>>();
  finalize_kernel<<<16384, 256>>>(kph[0][0], kph[0][1]);

  // Layer 1 (K = 2048)
  convert_w_kernel<<<4096, 256>>>(W2, 2048 * 2048 / 4);
  gemm_bf16x3_kernel<<<dim3(HDIM / TN, BATCH / TM), 256, GEMM_DYN_SMEM>>>(
      b2, 2048, kno[1][0], kno[1][1]);
  colsum_kernel<<<64, 256>>>();
  thermal_kernel<<<2, 1024>>>(0);
  thermal_matvec_kernel<<<16, 128>>>();

  finalize_out_kernel<<<8192, 256>>>(Wout, bout, out, kph[1][0], kph[1][1]);
}

// round 8
// speedup vs baseline: 1.8274x; 1.1332x over previous
#include <cuda_runtime.h>
#include <cuda_bf16.h>
#include <cstdint>

// ---------------------------------------------------------------------------
// PhotonicNeuralNetwork — B=8192, D_in=1024, H=2048, D_out=2, fp32.
// GEMMs on mma.sync bf16 (HMMA) with bf16x3 split precision, 512-thread CTAs.
// Exact JAX threefry/erfinv noise reproduction.
// ---------------------------------------------------------------------------

#define BATCH 8192
#define HDIM  2048

__device__ __align__(16) float         g_bufB[BATCH * HDIM];
__device__ __align__(16) __nv_bfloat16 g_Ahi[BATCH * HDIM];
__device__ __align__(16) __nv_bfloat16 g_Alo[BATCH * HDIM];
__device__ __align__(16) __nv_bfloat16 g_Whi[HDIM * HDIM];
__device__ __align__(16) __nv_bfloat16 g_Wlo[HDIM * HDIM];
__device__ __align__(16) float g_part[512 * HDIM];
__device__ __align__(16) float g_cs[HDIM];
__device__ __align__(16) float g_thermal2[2][HDIM];
__device__ __align__(16) float g_tn[HDIM];

// ---------------------------------------------------------------------------
// Threefry-2x32, exact JAX round/key schedule.
// ---------------------------------------------------------------------------
__host__ __device__ __forceinline__ uint32_t rotl32(uint32_t x, uint32_t r) {
#if defined(__CUDA_ARCH__)
  return __funnelshift_l(x, x, r);
#else
  return (x << r) | (x >> (32u - r));
#endif
}

__host__ __device__ __forceinline__ void threefry2x32(
    uint32_t k0, uint32_t k1, uint32_t x0, uint32_t x1,
    uint32_t& o0, uint32_t& o1) {
  uint32_t ks2 = 0x1BD11BDAu ^ k0 ^ k1;
  x0 += k0; x1 += k1;
#define TF_ROUND(r) { x0 += x1; x1 = rotl32(x1, r); x1 ^= x0; }
  TF_ROUND(13u) TF_ROUND(15u) TF_ROUND(26u) TF_ROUND(6u)
  x0 += k1;  x1 += ks2 + 1u;
  TF_ROUND(17u) TF_ROUND(29u) TF_ROUND(16u) TF_ROUND(24u)
  x0 += ks2; x1 += k0 + 2u;
  TF_ROUND(13u) TF_ROUND(15u) TF_ROUND(26u) TF_ROUND(6u)
  x0 += k0;  x1 += k1 + 3u;
  TF_ROUND(17u) TF_ROUND(29u) TF_ROUND(16u) TF_ROUND(24u)
  x0 += k1;  x1 += ks2 + 4u;
  TF_ROUND(13u) TF_ROUND(15u) TF_ROUND(26u) TF_ROUND(6u)
  x0 += ks2; x1 += k0 + 5u;
#undef TF_ROUND
  o0 = x0; o1 = x1;
}

__device__ __forceinline__ float xla_erfinv(float x) {
  float w = -log1pf(-x * x);
  float p;
  if (w < 5.0f) {
    w -= 2.5f;
    p = 2.81022636e-08f;
    p = fmaf(p, w, 3.43273939e-07f);
    p = fmaf(p, w, -3.5233877e-06f);
    p = fmaf(p, w, -4.39150654e-06f);
    p = fmaf(p, w, 0.00021858087f);
    p = fmaf(p, w, -0.00125372503f);
    p = fmaf(p, w, -0.00417768164f);
    p = fmaf(p, w, 0.246640727f);
    p = fmaf(p, w, 1.50140941f);
  } else {
    w = sqrtf(w) - 3.0f;
    p = -0.000200214257f;
    p = fmaf(p, w, 0.000100950558f);
    p = fmaf(p, w, 0.00134934322f);
    p = fmaf(p, w, -0.00367342844f);
    p = fmaf(p, w, 0.00573950773f);
    p = fmaf(p, w, -0.0076224613f);
    p = fmaf(p, w, 0.00943887047f);
    p = fmaf(p, w, 1.00167406f);
    p = fmaf(p, w, 2.83297682f);
  }
  return p * x;
}

__device__ __forceinline__ float jax_normal(uint32_t k0, uint32_t k1, uint32_t idx) {
  uint32_t o0, o1;
  threefry2x32(k0, k1, 0u, idx, o0, o1);
  uint32_t bits = o0 ^ o1;
  float f = __uint_as_float((bits >> 9) | 0x3f800000u) - 1.0f;
  const float lo = __uint_as_float(0xBF7FFFFFu);
  float u = fmaxf(fmaf(f, 2.0f, lo), lo);
  return 1.41421354f * xla_erfinv(u);
}

// ---------------------------------------------------------------------------
// PTX helpers (base-sm_100-safe)
// ---------------------------------------------------------------------------
__device__ __forceinline__ uint32_t smem_u32(const void* p) {
  uint32_t a;
  asm("{ .reg .u64 t; cvta.to.shared.u64 t, %1; cvt.u32.u64 %0, t; }"
      : "=r"(a) : "l"(p));
  return a;
}

__device__ __forceinline__ void cp16(uint32_t dst, const void* src) {
  asm volatile("cp.async.cg.shared.global [%0], [%1], 16;"
               :: "r"(dst), "l"(src) : "memory");
}

__device__ __forceinline__ void ldsm_x4(uint32_t* r, uint32_t addr) {
  asm volatile("ldmatrix.sync.aligned.m8n8.x4.shared.b16 {%0,%1,%2,%3}, [%4];"
               : "=r"(r[0]), "=r"(r[1]), "=r"(r[2]), "=r"(r[3]) : "r"(addr));
}

__device__ __forceinline__ void mma_bf16(float* d, const uint32_t* a,
                                         const uint32_t* b) {
  asm volatile(
      "mma.sync.aligned.m16n8k16.row.col.f32.bf16.bf16.f32 "
      "{%0,%1,%2,%3}, {%4,%5,%6,%7}, {%8,%9}, {%0,%1,%2,%3};"
      : "+f"(d[0]), "+f"(d[1]), "+f"(d[2]), "+f"(d[3])
      : "r"(a[0]), "r"(a[1]), "r"(a[2]), "r"(a[3]), "r"(b[0]), "r"(b[1]));
}

// ---------------------------------------------------------------------------
// bf16 hi/lo split converters
// ---------------------------------------------------------------------------
__device__ __forceinline__ void split_bf16(float v, __nv_bfloat16& h, __nv_bfloat16& l) {
  h = __float2bfloat16(v);
  l = __float2bfloat16(v - __bfloat162float(h));
}

__global__ void convert_w_kernel(const float* __restrict__ W, int n4) {
  int gi = blockIdx.x * blockDim.x + threadIdx.x;
  if (gi >= n4) return;
  float4 v = reinterpret_cast<const float4*>(W)[gi];
  float vv[4] = {v.x, v.y, v.z, v.w};
  __nv_bfloat16 h[4], l[4];
#pragma unroll
  for (int c = 0; c < 4; ++c) split_bf16(vv[c], h[c], l[c]);
  __nv_bfloat162* H = reinterpret_cast<__nv_bfloat162*>(g_Whi);
  __nv_bfloat162* L = reinterpret_cast<__nv_bfloat162*>(g_Wlo);
  H[2 * gi]     = __halves2bfloat162(h[0], h[1]);
  H[2 * gi + 1] = __halves2bfloat162(h[2], h[3]);
  L[2 * gi]     = __halves2bfloat162(l[0], l[1]);
  L[2 * gi + 1] = __halves2bfloat162(l[2], l[3]);
}

__global__ void tanh_in_kernel(const float* __restrict__ x) {
  int gi = blockIdx.x * blockDim.x + threadIdx.x;
  float4 v = reinterpret_cast<const float4*>(x)[gi];
  float vv[4] = {tanhf(v.x), tanhf(v.y), tanhf(v.z), tanhf(v.w)};
  __nv_bfloat16 h[4], l[4];
#pragma unroll
  for (int c = 0; c < 4; ++c) split_bf16(vv[c], h[c], l[c]);
  __nv_bfloat162* H = reinterpret_cast<__nv_bfloat162*>(g_Ahi);
  __nv_bfloat162* L = reinterpret_cast<__nv_bfloat162*>(g_Alo);
  H[2 * gi]     = __halves2bfloat162(h[0], h[1]);
  H[2 * gi + 1] = __halves2bfloat162(h[2], h[3]);
  L[2 * gi]     = __halves2bfloat162(l[0], l[1]);
  L[2 * gi + 1] = __halves2bfloat162(l[2], l[3]);
}

// ---------------------------------------------------------------------------
// HMMA GEMM: Y[m,n] = tanh(sum_k A[m,k]*W[n,k] + bias[n]) + 0.02*noise(m*2048+n)
// CTA 128x256, 512 threads (16 warps, 2x8), warp tile 64x32, BK=64, bf16x3.
// ---------------------------------------------------------------------------
#define TM 128
#define TN 256
#define CK 64
#define A_T (128 * 128)                   // 16 KB per A half
#define W_T (256 * 128)                   // 32 KB per W half
#define STAGE_BYTES (2 * A_T + 2 * W_T)   // 96 KB
#define GEMM_DYN_SMEM (1024 + 2 * STAGE_BYTES)

__global__ void __launch_bounds__(512, 1)
gemm_bf16x3_kernel(const float* __restrict__ bias, int K,
                   uint32_t nk0, uint32_t nk1) {
  extern __shared__ char dynsmem[];
  __shared__ float sBias[TN];

  const int tid  = threadIdx.x;
  const int wid  = tid >> 5;
  const int lane = tid & 31;
  const int bn   = blockIdx.x * TN;
  const int bm   = blockIdx.y * TM;
  const int wr   = wid & 1;    // 0..1 : 64 rows each
  const int wc   = wid >> 1;   // 0..7 : 32 cols each

  const uint32_t smem = (smem_u32(dynsmem) + 1023u) & ~1023u;

  if (tid < TN) sBias[tid] = bias[bn + tid];

  // stage loader: 512 threads, A 2 passes, W 4 passes, 16B each (hi+lo)
  const int lr = tid >> 3;  // 0..63
  const int lc = tid & 7;   // 16B chunk
  const uint32_t sw = (uint32_t)((lc ^ (lr & 7)) << 4);
  const __nv_bfloat16* Ahi = g_Ahi;
  const __nv_bfloat16* Alo = g_Alo;
  const __nv_bfloat16* Whi = g_Whi;
  const __nv_bfloat16* Wlo = g_Wlo;

  auto load_stage = [&](int s, int ck) {
    const uint32_t base = smem + (uint32_t)s * STAGE_BYTES;
    const size_t kcol = (size_t)ck * CK + (size_t)lc * 8;
#pragma unroll
    for (int q = 0; q < 2; ++q) {
      const int r = lr + 64 * q;
      const uint32_t doff = (uint32_t)r * 128u + sw;
      const size_t aoff = (size_t)(bm + r) * K + kcol;
      cp16(base + doff,       Ahi + aoff);
      cp16(base + A_T + doff, Alo + aoff);
    }
    const uint32_t wb = base + 2 * A_T;
#pragma unroll
    for (int q = 0; q < 4; ++q) {
      const int r = lr + 64 * q;
      const uint32_t doff = (uint32_t)r * 128u + sw;
      const size_t woff = (size_t)(bn + r) * K + kcol;
      cp16(wb + doff,       Whi + woff);
      cp16(wb + W_T + doff, Wlo + woff);
    }
    asm volatile("cp.async.commit_group;" ::: "memory");
  };

  // ldmatrix per-lane addressing
  const int aRow = wr * 64 + (lane & 15);
  const int aChk = lane >> 4;
  const uint32_t aSwz = (uint32_t)(lane & 7) << 4;
  // B x4: covers two n8 tiles (jp*16 .. jp*16+15) x k16
  const int bRow0 = wc * 32 + ((lane >> 4) << 3) + (lane & 7);
  const int bChk = (lane >> 3) & 1;
  const uint32_t bSwz = (uint32_t)(lane & 7) << 4;

  float acc[4][4][4];
#pragma unroll
  for (int i = 0; i < 4; ++i)
#pragma unroll
    for (int j = 0; j < 4; ++j)
#pragma unroll
      for (int t = 0; t < 4; ++t) acc[i][j][t] = 0.0f;

  const int nch = K / CK;
  load_stage(0, 0);

  for (int c = 0; c < nch; ++c) {
    const int s = c & 1;
    if (c + 1 < nch) {
      load_stage(s ^ 1, c + 1);
      asm volatile("cp.async.wait_group 1;" ::: "memory");
    } else {
      asm volatile("cp.async.wait_group 0;" ::: "memory");
    }
    __syncthreads();

    const uint32_t aHiB = smem + (uint32_t)s * STAGE_BYTES;
    const uint32_t aLoB = aHiB + A_T;
    const uint32_t wHiB = aHiB + 2 * A_T;
    const uint32_t wLoB = wHiB + W_T;

#pragma unroll
    for (int ks = 0; ks < 4; ++ks) {
      const uint32_t aOffC = ((uint32_t)((2 * ks + aChk) << 4)) ^ aSwz;
      const uint32_t bOffC = ((uint32_t)((2 * ks + bChk) << 4)) ^ bSwz;

      uint32_t wh[4][2], wl[4][2];
#pragma unroll
      for (int jp = 0; jp < 2; ++jp) {
        const uint32_t off = (uint32_t)(bRow0 + jp * 16) * 128u + bOffC;
        ldsm_x4(&wh[2 * jp][0], wHiB + off);
        ldsm_x4(&wl[2 * jp][0], wLoB + off);
      }
      uint32_t ahi[4][4];
#pragma unroll
      for (int i = 0; i < 4; ++i) {
        const uint32_t off = (uint32_t)(aRow + i * 16) * 128u + aOffC;
        ldsm_x4(ahi[i], aHiB + off);
      }
#pragma unroll
      for (int i = 0; i < 4; ++i)
#pragma unroll
        for (int j = 0; j < 4; ++j) mma_bf16(acc[i][j], ahi[i], wh[j]);
#pragma unroll
      for (int i = 0; i < 4; ++i)
#pragma unroll
        for (int j = 0; j < 4; ++j) mma_bf16(acc[i][j], ahi[i], wl[j]);
      uint32_t alo[4][4];
#pragma unroll
      for (int i = 0; i < 4; ++i) {
        const uint32_t off = (uint32_t)(aRow + i * 16) * 128u + aOffC;
        ldsm_x4(alo[i], aLoB + off);
      }
#pragma unroll
      for (int i = 0; i < 4; ++i)
#pragma unroll
        for (int j = 0; j < 4; ++j) mma_bf16(acc[i][j], alo[i], wh[j]);
    }
    __syncthreads();
  }

  // epilogue: bias + tanh + exact JAX noise
  const int r0 = bm + wr * 64 + (lane >> 2);
  const int c0l = wc * 32 + 2 * (lane & 3);
#pragma unroll
  for (int i = 0; i < 4; ++i) {
#pragma unroll
    for (int j = 0; j < 4; ++j) {
      const int cc = c0l + j * 8;
      const int cg = bn + cc;
#pragma unroll
      for (int hrow = 0; hrow < 2; ++hrow) {
        const int m = r0 + i * 16 + hrow * 8;
        const uint32_t nb = (uint32_t)m * 2048u + (uint32_t)cg;
        float v0 = acc[i][j][2 * hrow]     + sBias[cc];
        float v1 = acc[i][j][2 * hrow + 1] + sBias[cc + 1];
        v0 = tanhf(v0) + jax_normal(nk0, nk1, nb)     * 0.02f;
        v1 = tanhf(v1) + jax_normal(nk0, nk1, nb + 1) * 0.02f;
        *reinterpret_cast<float2*>(g_bufB + (size_t)m * HDIM + cg) =
            make_float2(v0, v1);
      }
    }
  }
}

// ---------------------------------------------------------------------------
// colsum two-phase: 512 partial blocks of 16 rows, then deterministic reduce.
// ---------------------------------------------------------------------------
__global__ void colsum_part_kernel() {
  const int b = blockIdx.x;       // 512
  const int t = threadIdx.x;      // 256
  const float* base = g_bufB + (size_t)b * 16 * HDIM;
#pragma unroll
  for (int p = 0; p < 8; ++p) {
    const int c = t + 256 * p;
    float s = 0.0f;
#pragma unroll
    for (int r = 0; r < 16; ++r) s += fabsf(base[(size_t)r * HDIM + c]);
    g_part[b * HDIM + c] = s;
  }
}

__global__ void colsum_reduce_kernel() {
  const int c = blockIdx.x * 256 + threadIdx.x;  // grid 8 x 256
  float s = 0.0f;
  for (int p = 0; p < 512; ++p) s += g_part[p * HDIM + c];
  g_cs[c] = s;
}

// ---------------------------------------------------------------------------
// thermal EMA (ping-pong) fused with the crosstalk matvec.
// g_tn[j] = 0.05 * sum_i th[i] * (i==j ? 0 : 1/(i-j)^2)
// ---------------------------------------------------------------------------
__global__ void thermal_matvec_kernel(int cur, int first) {
  __shared__ float th[HDIM];
  __shared__ float rec[HDIM];
  const int tid = threadIdx.x;  // 128
  const int prev = cur ^ 1;
  for (int i = tid; i < HDIM; i += 128) {
    float lt = g_cs[i] * 0.05f;
    float tv = first ? (0.3f * lt) : (0.7f * g_thermal2[prev][i] + 0.3f * lt);
    th[i] = tv;
    if (blockIdx.x == 0) g_thermal2[cur][i] = tv;
    float d = (float)i;
    rec[i] = (i == 0) ? 0.0f : (1.0f / (d * d));
  }
  __syncthreads();
  const int j = blockIdx.x * 128 + tid;
  float acc = 0.0f;
  for (int i = 0; i < HDIM; ++i) {
    int d = i - j; d = d < 0 ? -d : d;
    acc += th[i] * rec[d];
  }
  g_tn[j] = acc * 0.05f;
}

// ---------------------------------------------------------------------------
// finalize (layer 0): x = y + tn; phase noise; split to bf16 hi/lo for GEMM2.
// ---------------------------------------------------------------------------
__global__ void finalize_kernel(uint32_t kp0, uint32_t kp1) {
  const int gi = blockIdx.x * blockDim.x + threadIdx.x;
  const int idx = gi << 2;
  float4 y = *reinterpret_cast<const float4*>(g_bufB + idx);
  float4 t = *reinterpret_cast<const float4*>(g_tn + (idx & 2047));
  float v[4] = {y.x, y.y, y.z, y.w};
  float tv[4] = {t.x, t.y, t.z, t.w};
  __nv_bfloat16 h[4], l[4];
#pragma unroll
  for (int c = 0; c < 4; ++c) {
    float xx = v[c] + tv[c];
    float ph = jax_normal(kp0, kp1, (uint32_t)(idx + c)) * 0.03f;
    xx = xx + (xx * cosf(ph) - xx) * 0.03f;
    split_bf16(xx, h[c], l[c]);
  }
  __nv_bfloat162* H = reinterpret_cast<__nv_bfloat162*>(g_Ahi);
  __nv_bfloat162* L = reinterpret_cast<__nv_bfloat162*>(g_Alo);
  H[2 * gi]     = __halves2bfloat162(h[0], h[1]);
  H[2 * gi + 1] = __halves2bfloat162(h[2], h[3]);
  L[2 * gi]     = __halves2bfloat162(l[0], l[1]);
  L[2 * gi + 1] = __halves2bfloat162(l[2], l[3]);
}

// ---------------------------------------------------------------------------
// finalize (layer 1) fused with output GEMM (D_out=2).
// ---------------------------------------------------------------------------
__global__ void __launch_bounds__(256)
finalize_out_kernel(const float* __restrict__ Wout,
                    const float* __restrict__ bout,
                    float* __restrict__ out,
                    uint32_t kp0, uint32_t kp1) {
  const int b = blockIdx.x;
  const int tid = threadIdx.x;
  const float* row = g_bufB + (size_t)b * 2048;
  float a0 = 0.0f, a1 = 0.0f;
#pragma unroll
  for (int q = 0; q < 2; ++q) {
    const int h = (tid + q * 256) * 4;
    float4 y  = *reinterpret_cast<const float4*>(row + h);
    float4 t  = *reinterpret_cast<const float4*>(g_tn + h);
    float4 w0 = *reinterpret_cast<const float4*>(Wout + h);
    float4 w1 = *reinterpret_cast<const float4*>(Wout + 2048 + h);
    float yv[4] = {y.x, y.y, y.z, y.w};
    float tv[4] = {t.x, t.y, t.z, t.w};
    float w0v[4] = {w0.x, w0.y, w0.z, w0.w};
    float w1v[4] = {w1.x, w1.y, w1.z, w1.w};
#pragma unroll
    for (int c = 0; c < 4; ++c) {
      float xx = yv[c] + tv[c];
      float ph = jax_normal(kp0, kp1, (uint32_t)(b * 2048 + h + c)) * 0.03f;
      xx = xx + (xx * cosf(ph) - xx) * 0.03f;
      a0 += xx * w0v[c];
      a1 += xx * w1v[c];
    }
  }
  __shared__ float s0[256];
  __shared__ float s1[256];
  s0[tid] = a0; s1[tid] = a1;
  __syncthreads();
#pragma unroll
  for (int off = 128; off > 0; off >>= 1) {
    if (tid < off) { s0[tid] += s0[tid + off]; s1[tid] += s1[tid + off]; }
    __syncthreads();
  }
  if (tid == 0) {
    out[2 * b + 0] = s0[0] + bout[0];
    out[2 * b + 1] = s1[0] + bout[1];
  }
}

// ---------------------------------------------------------------------------
// Launch
// ---------------------------------------------------------------------------
extern "C" void kernel_launch(void* const* d_in, const int* in_sizes, int n_in,
                              void* d_out, int out_size) {
  (void)in_sizes; (void)n_in; (void)out_size;
  const float* x    = (const float*)d_in[0];
  const float* W1   = (const float*)d_in[1];
  const float* b1   = (const float*)d_in[2];
  const float* W2   = (const float*)d_in[3];
  const float* b2   = (const float*)d_in[4];
  const float* Wout = (const float*)d_in[5];
  const float* bout = (const float*)d_in[6];
  float* out = (float*)d_out;

  cudaFuncSetAttribute(gemm_bf16x3_kernel,
                       cudaFuncAttributeMaxDynamicSharedMemorySize,
                       GEMM_DYN_SMEM);

  uint32_t kno[2][2], kph[2][2];
  for (int li = 0; li < 2; ++li) {
    threefry2x32(0u, 42u, 0u, (uint32_t)(2 * li),     kno[li][0], kno[li][1]);
    threefry2x32(0u, 42u, 0u, (uint32_t)(2 * li + 1), kph[li][0], kph[li][1]);
  }

  // Layer 0 (K = 1024)
  convert_w_kernel<<<2048, 256>>>(W1, 2048 * 1024 / 4);
  tanh_in_kernel<<<8192, 256>>>(x);
  gemm_bf16x3_kernel<<<dim3(HDIM / TN, BATCH / TM), 512, GEMM_DYN_SMEM>>>(
      b1, 1024, kno[0][0], kno[0][1]);
  colsum_part_kernel<<<512, 256>>>();
  colsum_reduce_kernel<<<8, 256>>>();
  thermal_matvec_kernel<<<16, 128>>>(0, 1);
  finalize_kernel<<<16384, 256>>>(kph[0][0], kph[0][1]);

  // Layer 1 (K = 2048)
  convert_w_kernel<<<4096, 256>>>(W2, 2048 * 2048 / 4);
  gemm_bf16x3_kernel<<<dim3(HDIM / TN, BATCH / TM), 512, GEMM_DYN_SMEM>>>(
      b2, 2048, kno[1][0], kno[1][1]);
  colsum_part_kernel<<<512, 256>>>();
  colsum_reduce_kernel<<<8, 256>>>();
  thermal_matvec_kernel<<<16, 128>>>(1, 0);

  finalize_out_kernel<<<8192, 256>>>(Wout, bout, out, kph[1][0], kph[1][1]);
}

// round 13
// speedup vs baseline: 2.2588x; 1.2361x over previous
#include <cuda_runtime.h>
#include <cuda_fp16.h>
#include <cstdint>

// ---------------------------------------------------------------------------
// PhotonicNeuralNetwork — B=8192, D_in=1024, H=2048, D_out=2, fp32.
// GEMMs on mma.sync fp16 (HMMA k16) with A split into two fp16 limbs and W
// in single fp16 (2 MMAs per k16). Layer-2 thermal offset handled exactly in
// fp32 (tn@W2 matvec folded into the bias). Exact JAX threefry/erfinv noise.
// FIX vs R12: g_colAdd device address obtained via cudaGetSymbolAddress —
// passing a __device__ symbol directly from host is UB and was the cause of
// the constant 128 MiB "allocation" failures in rounds 9-12.
// ---------------------------------------------------------------------------

#define BATCH 8192
#define HDIM  2048

__device__ __align__(16) float  g_bufB[BATCH * HDIM];
__device__ __align__(16) __half g_Ahi[BATCH * HDIM];
__device__ __align__(16) __half g_Alo[BATCH * HDIM];
__device__ __align__(16) __half g_W[HDIM * HDIM];
__device__ __align__(16) float g_part[512 * HDIM];
__device__ __align__(16) float g_cs[HDIM];
__device__ __align__(16) float g_thermal2[2][HDIM];
__device__ __align__(16) float g_tn[HDIM];
__device__ __align__(16) float g_colAdd[HDIM];

// ---------------------------------------------------------------------------
// Threefry-2x32, exact JAX round/key schedule.
// ---------------------------------------------------------------------------
__host__ __device__ __forceinline__ uint32_t rotl32(uint32_t x, uint32_t r) {
#if defined(__CUDA_ARCH__)
  return __funnelshift_l(x, x, r);
#else
  return (x << r) | (x >> (32u - r));
#endif
}

__host__ __device__ __forceinline__ void threefry2x32(
    uint32_t k0, uint32_t k1, uint32_t x0, uint32_t x1,
    uint32_t& o0, uint32_t& o1) {
  uint32_t ks2 = 0x1BD11BDAu ^ k0 ^ k1;
  x0 += k0; x1 += k1;
#define TF_ROUND(r) { x0 += x1; x1 = rotl32(x1, r); x1 ^= x0; }
  TF_ROUND(13u) TF_ROUND(15u) TF_ROUND(26u) TF_ROUND(6u)
  x0 += k1;  x1 += ks2 + 1u;
  TF_ROUND(17u) TF_ROUND(29u) TF_ROUND(16u) TF_ROUND(24u)
  x0 += ks2; x1 += k0 + 2u;
  TF_ROUND(13u) TF_ROUND(15u) TF_ROUND(26u) TF_ROUND(6u)
  x0 += k0;  x1 += k1 + 3u;
  TF_ROUND(17u) TF_ROUND(29u) TF_ROUND(16u) TF_ROUND(24u)
  x0 += k1;  x1 += ks2 + 4u;
  TF_ROUND(13u) TF_ROUND(15u) TF_ROUND(26u) TF_ROUND(6u)
  x0 += ks2; x1 += k0 + 5u;
#undef TF_ROUND
  o0 = x0; o1 = x1;
}

__device__ __forceinline__ float xla_erfinv(float x) {
  float w = -log1pf(-x * x);
  float p;
  if (w < 5.0f) {
    w -= 2.5f;
    p = 2.81022636e-08f;
    p = fmaf(p, w, 3.43273939e-07f);
    p = fmaf(p, w, -3.5233877e-06f);
    p = fmaf(p, w, -4.39150654e-06f);
    p = fmaf(p, w, 0.00021858087f);
    p = fmaf(p, w, -0.00125372503f);
    p = fmaf(p, w, -0.00417768164f);
    p = fmaf(p, w, 0.246640727f);
    p = fmaf(p, w, 1.50140941f);
  } else {
    w = sqrtf(w) - 3.0f;
    p = -0.000200214257f;
    p = fmaf(p, w, 0.000100950558f);
    p = fmaf(p, w, 0.00134934322f);
    p = fmaf(p, w, -0.00367342844f);
    p = fmaf(p, w, 0.00573950773f);
    p = fmaf(p, w, -0.0076224613f);
    p = fmaf(p, w, 0.00943887047f);
    p = fmaf(p, w, 1.00167406f);
    p = fmaf(p, w, 2.83297682f);
  }
  return p * x;
}

__device__ __forceinline__ float jax_normal(uint32_t k0, uint32_t k1, uint32_t idx) {
  uint32_t o0, o1;
  threefry2x32(k0, k1, 0u, idx, o0, o1);
  uint32_t bits = o0 ^ o1;
  float f = __uint_as_float((bits >> 9) | 0x3f800000u) - 1.0f;
  const float lo = __uint_as_float(0xBF7FFFFFu);
  float u = fmaxf(fmaf(f, 2.0f, lo), lo);
  return 1.41421354f * xla_erfinv(u);
}

// ---------------------------------------------------------------------------
// PTX helpers (base-sm_100-safe)
// ---------------------------------------------------------------------------
__device__ __forceinline__ uint32_t smem_u32(const void* p) {
  uint32_t a;
  asm("{ .reg .u64 t; cvta.to.shared.u64 t, %1; cvt.u32.u64 %0, t; }"
      : "=r"(a) : "l"(p));
  return a;
}

__device__ __forceinline__ void cp16(uint32_t dst, const void* src) {
  asm volatile("cp.async.cg.shared.global [%0], [%1], 16;"
               :: "r"(dst), "l"(src) : "memory");
}

__device__ __forceinline__ void ldsm_x4(uint32_t* r, uint32_t addr) {
  asm volatile("ldmatrix.sync.aligned.m8n8.x4.shared.b16 {%0,%1,%2,%3}, [%4];"
               : "=r"(r[0]), "=r"(r[1]), "=r"(r[2]), "=r"(r[3]) : "r"(addr));
}

__device__ __forceinline__ void mma_f16(float* d, const uint32_t* a,
                                        const uint32_t* b) {
  asm volatile(
      "mma.sync.aligned.m16n8k16.row.col.f32.f16.f16.f32 "
      "{%0,%1,%2,%3}, {%4,%5,%6,%7}, {%8,%9}, {%0,%1,%2,%3};"
      : "+f"(d[0]), "+f"(d[1]), "+f"(d[2]), "+f"(d[3])
      : "r"(a[0]), "r"(a[1]), "r"(a[2]), "r"(a[3]), "r"(b[0]), "r"(b[1]));
}

// ---------------------------------------------------------------------------
// fp16 hi/lo split converters
// ---------------------------------------------------------------------------
__device__ __forceinline__ void split_fp16(float v, __half& h, __half& l) {
  h = __float2half_rn(v);
  l = __float2half_rn(v - __half2float(h));
}

__global__ void convert_w_kernel(const float* __restrict__ W, int n4) {
  int gi = blockIdx.x * blockDim.x + threadIdx.x;
  if (gi >= n4) return;
  float4 v = reinterpret_cast<const float4*>(W)[gi];
  __half2* Wp = reinterpret_cast<__half2*>(g_W);
  Wp[2 * gi]     = __halves2half2(__float2half_rn(v.x), __float2half_rn(v.y));
  Wp[2 * gi + 1] = __halves2half2(__float2half_rn(v.z), __float2half_rn(v.w));
}

__global__ void tanh_in_kernel(const float* __restrict__ x) {
  int gi = blockIdx.x * blockDim.x + threadIdx.x;
  float4 v = reinterpret_cast<const float4*>(x)[gi];
  float vv[4] = {tanhf(v.x), tanhf(v.y), tanhf(v.z), tanhf(v.w)};
  __half h[4], l[4];
#pragma unroll
  for (int c = 0; c < 4; ++c) split_fp16(vv[c], h[c], l[c]);
  __half2* H = reinterpret_cast<__half2*>(g_Ahi);
  __half2* L = reinterpret_cast<__half2*>(g_Alo);
  H[2 * gi]     = __halves2half2(h[0], h[1]);
  H[2 * gi + 1] = __halves2half2(h[2], h[3]);
  L[2 * gi]     = __halves2half2(l[0], l[1]);
  L[2 * gi + 1] = __halves2half2(l[2], l[3]);
}

// ---------------------------------------------------------------------------
// HMMA GEMM: Y[m,n] = tanh(sum_k A[m,k]*W[n,k] + bias[n]) + 0.02*noise
// CTA 128x256, 512 threads (16 warps, 2x8), warp tile 64x32, BK=64 fp16.
// D = (Ahi + Alo) @ W_fp16 : 2 MMAs per k16. Structure = round-8 kernel.
// ---------------------------------------------------------------------------
#define TM 128
#define TN 256
#define CK 64
#define A_T (128 * 128)                   // 16 KB per A limb
#define W_T (256 * 128)                   // 32 KB single W tile
#define STAGE_BYTES (2 * A_T + W_T)       // 64 KB
#define GEMM_DYN_SMEM (1024 + 2 * STAGE_BYTES)

__global__ void __launch_bounds__(512, 1)
gemm_fp16x2_kernel(const float* __restrict__ bias, int K,
                   uint32_t nk0, uint32_t nk1) {
  extern __shared__ char dynsmem[];
  __shared__ float sBias[TN];

  const int tid  = threadIdx.x;
  const int wid  = tid >> 5;
  const int lane = tid & 31;
  const int bn   = blockIdx.x * TN;
  const int bm   = blockIdx.y * TM;
  const int wr   = wid & 1;    // 0..1 : 64 rows each
  const int wc   = wid >> 1;   // 0..7 : 32 cols each

  const uint32_t smem = (smem_u32(dynsmem) + 1023u) & ~1023u;

  if (tid < TN) sBias[tid] = bias[bn + tid];

  // stage loader: rows are 128B, XOR swizzle on 16B chunks.
  const int lr = tid >> 3;  // 0..63
  const int lc = tid & 7;
  const uint32_t sw = (uint32_t)((lc ^ (lr & 7)) << 4);
  const __half* Ahi = g_Ahi;
  const __half* Alo = g_Alo;
  const __half* Wp  = g_W;

  auto load_stage = [&](int s, int ck) {
    const uint32_t base = smem + (uint32_t)s * STAGE_BYTES;
    const size_t kcol = (size_t)ck * CK + (size_t)lc * 8;
#pragma unroll
    for (int q = 0; q < 2; ++q) {
      const int r = lr + 64 * q;
      const uint32_t doff = (uint32_t)r * 128u + sw;
      const size_t aoff = (size_t)(bm + r) * K + kcol;
      cp16(base + doff,       Ahi + aoff);
      cp16(base + A_T + doff, Alo + aoff);
    }
    const uint32_t wb = base + 2 * A_T;
#pragma unroll
    for (int q = 0; q < 4; ++q) {
      const int r = lr + 64 * q;
      const uint32_t doff = (uint32_t)r * 128u + sw;
      cp16(wb + doff, Wp + (size_t)(bn + r) * K + kcol);
    }
    asm volatile("cp.async.commit_group;" ::: "memory");
  };

  // ldmatrix per-lane addressing (verbatim from the passing round-8 kernel).
  const int aRow = wr * 64 + (lane & 15);
  const int aChk = lane >> 4;
  const uint32_t aSwz = (uint32_t)(lane & 7) << 4;
  const int bRow0 = wc * 32 + ((lane >> 4) << 3) + (lane & 7);
  const int bChk = (lane >> 3) & 1;
  const uint32_t bSwz = (uint32_t)(lane & 7) << 4;

  float acc[4][4][4];
#pragma unroll
  for (int i = 0; i < 4; ++i)
#pragma unroll
    for (int j = 0; j < 4; ++j)
#pragma unroll
      for (int t = 0; t < 4; ++t) acc[i][j][t] = 0.0f;

  const int nch = K / CK;
  load_stage(0, 0);

  for (int c = 0; c < nch; ++c) {
    const int s = c & 1;
    if (c + 1 < nch) {
      load_stage(s ^ 1, c + 1);
      asm volatile("cp.async.wait_group 1;" ::: "memory");
    } else {
      asm volatile("cp.async.wait_group 0;" ::: "memory");
    }
    __syncthreads();

    const uint32_t aHiB = smem + (uint32_t)s * STAGE_BYTES;
    const uint32_t aLoB = aHiB + A_T;
    const uint32_t wB   = aHiB + 2 * A_T;

#pragma unroll
    for (int ks = 0; ks < 4; ++ks) {
      const uint32_t aOffC = ((uint32_t)((2 * ks + aChk) << 4)) ^ aSwz;
      const uint32_t bOffC = ((uint32_t)((2 * ks + bChk) << 4)) ^ bSwz;

      uint32_t wh[4][2];
#pragma unroll
      for (int jp = 0; jp < 2; ++jp) {
        const uint32_t off = (uint32_t)(bRow0 + jp * 16) * 128u + bOffC;
        ldsm_x4(&wh[2 * jp][0], wB + off);
      }
      uint32_t ahi[4][4];
#pragma unroll
      for (int i = 0; i < 4; ++i) {
        const uint32_t off = (uint32_t)(aRow + i * 16) * 128u + aOffC;
        ldsm_x4(ahi[i], aHiB + off);
      }
#pragma unroll
      for (int i = 0; i < 4; ++i)
#pragma unroll
        for (int j = 0; j < 4; ++j) mma_f16(acc[i][j], ahi[i], wh[j]);
      uint32_t alo[4][4];
#pragma unroll
      for (int i = 0; i < 4; ++i) {
        const uint32_t off = (uint32_t)(aRow + i * 16) * 128u + aOffC;
        ldsm_x4(alo[i], aLoB + off);
      }
#pragma unroll
      for (int i = 0; i < 4; ++i)
#pragma unroll
        for (int j = 0; j < 4; ++j) mma_f16(acc[i][j], alo[i], wh[j]);
    }
    __syncthreads();
  }

  // epilogue: bias + tanh + exact JAX noise
  const int r0 = bm + wr * 64 + (lane >> 2);
  const int c0l = wc * 32 + 2 * (lane & 3);
#pragma unroll
  for (int i = 0; i < 4; ++i) {
#pragma unroll
    for (int j = 0; j < 4; ++j) {
      const int cc = c0l + j * 8;
      const int cg = bn + cc;
#pragma unroll
      for (int hrow = 0; hrow < 2; ++hrow) {
        const int m = r0 + i * 16 + hrow * 8;
        const uint32_t nb = (uint32_t)m * 2048u + (uint32_t)cg;
        float v0 = acc[i][j][2 * hrow]     + sBias[cc];
        float v1 = acc[i][j][2 * hrow + 1] + sBias[cc + 1];
        v0 = tanhf(v0) + jax_normal(nk0, nk1, nb)     * 0.02f;
        v1 = tanhf(v1) + jax_normal(nk0, nk1, nb + 1) * 0.02f;
        *reinterpret_cast<float2*>(g_bufB + (size_t)m * HDIM + cg) =
            make_float2(v0, v1);
      }
    }
  }
}

// ---------------------------------------------------------------------------
// colsum two-phase (deterministic) — unchanged from round-8.
// ---------------------------------------------------------------------------
__global__ void colsum_part_kernel() {
  const int b = blockIdx.x;
  const int t = threadIdx.x;
  const float* base = g_bufB + (size_t)b * 16 * HDIM;
#pragma unroll
  for (int p = 0; p < 8; ++p) {
    const int c = t + 256 * p;
    float s = 0.0f;
#pragma unroll
    for (int r = 0; r < 16; ++r) s += fabsf(base[(size_t)r * HDIM + c]);
    g_part[b * HDIM + c] = s;
  }
}

__global__ void colsum_reduce_kernel() {
  const int c = blockIdx.x * 256 + threadIdx.x;
  float s = 0.0f;
  for (int p = 0; p < 512; ++p) s += g_part[p * HDIM + c];
  g_cs[c] = s;
}

// ---------------------------------------------------------------------------
// thermal EMA (ping-pong) fused with the crosstalk matvec — unchanged.
// ---------------------------------------------------------------------------
__global__ void thermal_matvec_kernel(int cur, int first) {
  __shared__ float th[HDIM];
  __shared__ float rec[HDIM];
  const int tid = threadIdx.x;  // 128
  const int prev = cur ^ 1;
  for (int i = tid; i < HDIM; i += 128) {
    float lt = g_cs[i] * 0.05f;
    float tv = first ? (0.3f * lt) : (0.7f * g_thermal2[prev][i] + 0.3f * lt);
    th[i] = tv;
    if (blockIdx.x == 0) g_thermal2[cur][i] = tv;
    float d = (float)i;
    rec[i] = (i == 0) ? 0.0f : (1.0f / (d * d));
  }
  __syncthreads();
  const int j = blockIdx.x * 128 + tid;
  float acc = 0.0f;
  for (int i = 0; i < HDIM; ++i) {
    int d = i - j; d = d < 0 ? -d : d;
    acc += th[i] * rec[d];
  }
  g_tn[j] = acc * 0.05f;
}

// colAdd[n] = b[n] + sum_h tn[h]*W[n,h]  (exact fp32 thermal-offset folding).
__global__ void tnw_kernel(const float* __restrict__ W,
                           const float* __restrict__ b) {
  const int wid = threadIdx.x >> 5;
  const int lane = threadIdx.x & 31;
  const int n = blockIdx.x * 8 + wid;
  const float* row = W + (size_t)n * HDIM;
  float s = 0.0f;
  for (int h = lane; h < HDIM; h += 32) s += g_tn[h] * row[h];
#pragma unroll
  for (int o = 16; o > 0; o >>= 1) s += __shfl_xor_sync(0xFFFFFFFFu, s, o);
  if (lane == 0) g_colAdd[n] = s + b[n];
}

// ---------------------------------------------------------------------------
// finalize (layer 0): z = y + tn; phase noise; split (x - tn) to fp16 limbs.
// ---------------------------------------------------------------------------
__global__ void finalize_kernel(uint32_t kp0, uint32_t kp1) {
  const int gi = blockIdx.x * blockDim.x + threadIdx.x;
  const int idx = gi << 2;
  float4 y = *reinterpret_cast<const float4*>(g_bufB + idx);
  float4 t = *reinterpret_cast<const float4*>(g_tn + (idx & 2047));
  float v[4] = {y.x, y.y, y.z, y.w};
  float tv[4] = {t.x, t.y, t.z, t.w};
  __half h[4], l[4];
#pragma unroll
  for (int c = 0; c < 4; ++c) {
    float z = v[c] + tv[c];
    float ph = jax_normal(kp0, kp1, (uint32_t)(idx + c)) * 0.03f;
    float xx = z + (z * cosf(ph) - z) * 0.03f;
    split_fp16(xx - tv[c], h[c], l[c]);
  }
  __half2* H = reinterpret_cast<__half2*>(g_Ahi);
  __half2* L = reinterpret_cast<__half2*>(g_Alo);
  H[2 * gi]     = __halves2half2(h[0], h[1]);
  H[2 * gi + 1] = __halves2half2(h[2], h[3]);
  L[2 * gi]     = __halves2half2(l[0], l[1]);
  L[2 * gi + 1] = __halves2half2(l[2], l[3]);
}

// ---------------------------------------------------------------------------
// finalize (layer 1) fused with output GEMM (D_out=2) — unchanged.
// ---------------------------------------------------------------------------
__global__ void __launch_bounds__(256)
finalize_out_kernel(const float* __restrict__ Wout,
                    const float* __restrict__ bout,
                    float* __restrict__ out,
                    uint32_t kp0, uint32_t kp1) {
  const int b = blockIdx.x;
  const int tid = threadIdx.x;
  const float* row = g_bufB + (size_t)b * 2048;
  float a0 = 0.0f, a1 = 0.0f;
#pragma unroll
  for (int q = 0; q < 2; ++q) {
    const int h = (tid + q * 256) * 4;
    float4 y  = *reinterpret_cast<const float4*>(row + h);
    float4 t  = *reinterpret_cast<const float4*>(g_tn + h);
    float4 w0 = *reinterpret_cast<const float4*>(Wout + h);
    float4 w1 = *reinterpret_cast<const float4*>(Wout + 2048 + h);
    float yv[4] = {y.x, y.y, y.z, y.w};
    float tv[4] = {t.x, t.y, t.z, t.w};
    float w0v[4] = {w0.x, w0.y, w0.z, w0.w};
    float w1v[4] = {w1.x, w1.y, w1.z, w1.w};
#pragma unroll
    for (int c = 0; c < 4; ++c) {
      float xx = yv[c] + tv[c];
      float ph = jax_normal(kp0, kp1, (uint32_t)(b * 2048 + h + c)) * 0.03f;
      xx = xx + (xx * cosf(ph) - xx) * 0.03f;
      a0 += xx * w0v[c];
      a1 += xx * w1v[c];
    }
  }
  __shared__ float s0[256];
  __shared__ float s1[256];
  s0[tid] = a0; s1[tid] = a1;
  __syncthreads();
#pragma unroll
  for (int off = 128; off > 0; off >>= 1) {
    if (tid < off) { s0[tid] += s0[tid + off]; s1[tid] += s1[tid + off]; }
    __syncthreads();
  }
  if (tid == 0) {
    out[2 * b + 0] = s0[0] + bout[0];
    out[2 * b + 1] = s1[0] + bout[1];
  }
}

// ---------------------------------------------------------------------------
// Launch
// ---------------------------------------------------------------------------
extern "C" void kernel_launch(void* const* d_in, const int* in_sizes, int n_in,
                              void* d_out, int out_size) {
  (void)in_sizes; (void)n_in; (void)out_size;
  const float* x    = (const float*)d_in[0];
  const float* W1   = (const float*)d_in[1];
  const float* b1   = (const float*)d_in[2];
  const float* W2   = (const float*)d_in[3];
  const float* b2   = (const float*)d_in[4];
  const float* Wout = (const float*)d_in[5];
  const float* bout = (const float*)d_in[6];
  float* out = (float*)d_out;

  cudaFuncSetAttribute(gemm_fp16x2_kernel,
                       cudaFuncAttributeMaxDynamicSharedMemorySize,
                       GEMM_DYN_SMEM);

  // Device address of g_colAdd (passing the __device__ symbol directly from
  // host code is UB — this was the rounds-9..12 failure).
  float* colAddPtr = nullptr;
  cudaGetSymbolAddress((void**)&colAddPtr, g_colAdd);

  uint32_t kno[2][2], kph[2][2];
  for (int li = 0; li < 2; ++li) {
    threefry2x32(0u, 42u, 0u, (uint32_t)(2 * li),     kno[li][0], kno[li][1]);
    threefry2x32(0u, 42u, 0u, (uint32_t)(2 * li + 1), kph[li][0], kph[li][1]);
  }

  const dim3 ggrid(HDIM / TN, BATCH / TM);  // 8 x 64

  // Layer 0 (K = 1024); bias = b1 (no thermal offset yet).
  convert_w_kernel<<<2048, 256>>>(W1, 2048 * 1024 / 4);
  tanh_in_kernel<<<8192, 256>>>(x);
  gemm_fp16x2_kernel<<<ggrid, 512, GEMM_DYN_SMEM>>>(b1, 1024,
                                                    kno[0][0], kno[0][1]);
  colsum_part_kernel<<<512, 256>>>();
  colsum_reduce_kernel<<<8, 256>>>();
  thermal_matvec_kernel<<<16, 128>>>(0, 1);
  tnw_kernel<<<256, 256>>>(W2, b2);
  finalize_kernel<<<16384, 256>>>(kph[0][0], kph[0][1]);

  // Layer 1 (K = 2048); bias = b2 + tn@W2^T (exact fp32), A offset-free.
  convert_w_kernel<<<4096, 256>>>(W2, 2048 * 2048 / 4);
  gemm_fp16x2_kernel<<<ggrid, 512, GEMM_DYN_SMEM>>>(colAddPtr, 2048,
                                                    kno[1][0], kno[1][1]);
  colsum_part_kernel<<<512, 256>>>();
  colsum_reduce_kernel<<<8, 256>>>();
  thermal_matvec_kernel<<<16, 128>>>(1, 0);

  finalize_out_kernel<<<8192, 256>>>(Wout, bout, out, kph[1][0], kph[1][1]);
}

// round 14
// speedup vs baseline: 2.8787x; 1.2744x over previous
#include <cuda_runtime.h>
#include <cuda_fp16.h>
#include <cstdint>

// ---------------------------------------------------------------------------
// PhotonicNeuralNetwork — B=8192, D_in=1024, H=2048, D_out=2, fp32.
// GEMMs on mma.sync fp16 (HMMA k16), single-fp16 A and W (1 MMA per k16).
// Error model calibrated in R13: W-quant alone gave 2.84e-5; adding A-quant
// (equal, independent) predicts ~4e-5 total — 25x under the 1e-3 threshold.
// Layer-2 thermal offset folded exactly in fp32 (tn@W2 matvec -> bias).
// Exact JAX threefry/erfinv noise. Base = passing round-13 kernel.
// ---------------------------------------------------------------------------

#define BATCH 8192
#define HDIM  2048

__device__ __align__(16) float  g_bufB[BATCH * HDIM];
__device__ __align__(16) __half g_A[BATCH * HDIM];
__device__ __align__(16) __half g_W[HDIM * HDIM];
__device__ __align__(16) float g_part[512 * HDIM];
__device__ __align__(16) float g_cs[HDIM];
__device__ __align__(16) float g_thermal2[2][HDIM];
__device__ __align__(16) float g_tn[HDIM];
__device__ __align__(16) float g_colAdd[HDIM];

// ---------------------------------------------------------------------------
// Threefry-2x32, exact JAX round/key schedule.
// ---------------------------------------------------------------------------
__host__ __device__ __forceinline__ uint32_t rotl32(uint32_t x, uint32_t r) {
#if defined(__CUDA_ARCH__)
  return __funnelshift_l(x, x, r);
#else
  return (x << r) | (x >> (32u - r));
#endif
}

__host__ __device__ __forceinline__ void threefry2x32(
    uint32_t k0, uint32_t k1, uint32_t x0, uint32_t x1,
    uint32_t& o0, uint32_t& o1) {
  uint32_t ks2 = 0x1BD11BDAu ^ k0 ^ k1;
  x0 += k0; x1 += k1;
#define TF_ROUND(r) { x0 += x1; x1 = rotl32(x1, r); x1 ^= x0; }
  TF_ROUND(13u) TF_ROUND(15u) TF_ROUND(26u) TF_ROUND(6u)
  x0 += k1;  x1 += ks2 + 1u;
  TF_ROUND(17u) TF_ROUND(29u) TF_ROUND(16u) TF_ROUND(24u)
  x0 += ks2; x1 += k0 + 2u;
  TF_ROUND(13u) TF_ROUND(15u) TF_ROUND(26u) TF_ROUND(6u)
  x0 += k0;  x1 += k1 + 3u;
  TF_ROUND(17u) TF_ROUND(29u) TF_ROUND(16u) TF_ROUND(24u)
  x0 += k1;  x1 += ks2 + 4u;
  TF_ROUND(13u) TF_ROUND(15u) TF_ROUND(26u) TF_ROUND(6u)
  x0 += ks2; x1 += k0 + 5u;
#undef TF_ROUND
  o0 = x0; o1 = x1;
}

__device__ __forceinline__ float xla_erfinv(float x) {
  float w = -log1pf(-x * x);
  float p;
  if (w < 5.0f) {
    w -= 2.5f;
    p = 2.81022636e-08f;
    p = fmaf(p, w, 3.43273939e-07f);
    p = fmaf(p, w, -3.5233877e-06f);
    p = fmaf(p, w, -4.39150654e-06f);
    p = fmaf(p, w, 0.00021858087f);
    p = fmaf(p, w, -0.00125372503f);
    p = fmaf(p, w, -0.00417768164f);
    p = fmaf(p, w, 0.246640727f);
    p = fmaf(p, w, 1.50140941f);
  } else {
    w = sqrtf(w) - 3.0f;
    p = -0.000200214257f;
    p = fmaf(p, w, 0.000100950558f);
    p = fmaf(p, w, 0.00134934322f);
    p = fmaf(p, w, -0.00367342844f);
    p = fmaf(p, w, 0.00573950773f);
    p = fmaf(p, w, -0.0076224613f);
    p = fmaf(p, w, 0.00943887047f);
    p = fmaf(p, w, 1.00167406f);
    p = fmaf(p, w, 2.83297682f);
  }
  return p * x;
}

__device__ __forceinline__ float jax_normal(uint32_t k0, uint32_t k1, uint32_t idx) {
  uint32_t o0, o1;
  threefry2x32(k0, k1, 0u, idx, o0, o1);
  uint32_t bits = o0 ^ o1;
  float f = __uint_as_float((bits >> 9) | 0x3f800000u) - 1.0f;
  const float lo = __uint_as_float(0xBF7FFFFFu);
  float u = fmaxf(fmaf(f, 2.0f, lo), lo);
  return 1.41421354f * xla_erfinv(u);
}

// ---------------------------------------------------------------------------
// PTX helpers (base-sm_100-safe)
// ---------------------------------------------------------------------------
__device__ __forceinline__ uint32_t smem_u32(const void* p) {
  uint32_t a;
  asm("{ .reg .u64 t; cvta.to.shared.u64 t, %1; cvt.u32.u64 %0, t; }"
      : "=r"(a) : "l"(p));
  return a;
}

__device__ __forceinline__ void cp16(uint32_t dst, const void* src) {
  asm volatile("cp.async.cg.shared.global [%0], [%1], 16;"
               :: "r"(dst), "l"(src) : "memory");
}

__device__ __forceinline__ void ldsm_x4(uint32_t* r, uint32_t addr) {
  asm volatile("ldmatrix.sync.aligned.m8n8.x4.shared.b16 {%0,%1,%2,%3}, [%4];"
               : "=r"(r[0]), "=r"(r[1]), "=r"(r[2]), "=r"(r[3]) : "r"(addr));
}

__device__ __forceinline__ void mma_f16(float* d, const uint32_t* a,
                                        const uint32_t* b) {
  asm volatile(
      "mma.sync.aligned.m16n8k16.row.col.f32.f16.f16.f32 "
      "{%0,%1,%2,%3}, {%4,%5,%6,%7}, {%8,%9}, {%0,%1,%2,%3};"
      : "+f"(d[0]), "+f"(d[1]), "+f"(d[2]), "+f"(d[3])
      : "r"(a[0]), "r"(a[1]), "r"(a[2]), "r"(a[3]), "r"(b[0]), "r"(b[1]));
}

// ---------------------------------------------------------------------------
// fp16 converters
// ---------------------------------------------------------------------------
__global__ void convert_w_kernel(const float* __restrict__ W, int n4) {
  int gi = blockIdx.x * blockDim.x + threadIdx.x;
  if (gi >= n4) return;
  float4 v = reinterpret_cast<const float4*>(W)[gi];
  __half2* Wp = reinterpret_cast<__half2*>(g_W);
  Wp[2 * gi]     = __halves2half2(__float2half_rn(v.x), __float2half_rn(v.y));
  Wp[2 * gi + 1] = __halves2half2(__float2half_rn(v.z), __float2half_rn(v.w));
}

__global__ void tanh_in_kernel(const float* __restrict__ x) {
  int gi = blockIdx.x * blockDim.x + threadIdx.x;
  float4 v = reinterpret_cast<const float4*>(x)[gi];
  __half2* A = reinterpret_cast<__half2*>(g_A);
  A[2 * gi]     = __halves2half2(__float2half_rn(tanhf(v.x)),
                                 __float2half_rn(tanhf(v.y)));
  A[2 * gi + 1] = __halves2half2(__float2half_rn(tanhf(v.z)),
                                 __float2half_rn(tanhf(v.w)));
}

// ---------------------------------------------------------------------------
// HMMA GEMM: Y[m,n] = tanh(sum_k A[m,k]*W[n,k] + bias[n]) + 0.02*noise
// CTA 128x256, 512 threads (16 warps, 2x8), warp tile 64x32, BK=64 fp16.
// Single fp16 A and W: 1 MMA per k16. Structure = round-13 kernel.
// ---------------------------------------------------------------------------
#define TM 128
#define TN 256
#define CK 64
#define A_T (128 * 128)                   // 16 KB A tile
#define W_T (256 * 128)                   // 32 KB W tile
#define STAGE_BYTES (A_T + W_T)           // 48 KB
#define GEMM_DYN_SMEM (1024 + 2 * STAGE_BYTES)

__global__ void __launch_bounds__(512, 1)
gemm_fp16_kernel(const float* __restrict__ bias, int K,
                 uint32_t nk0, uint32_t nk1) {
  extern __shared__ char dynsmem[];
  __shared__ float sBias[TN];

  const int tid  = threadIdx.x;
  const int wid  = tid >> 5;
  const int lane = tid & 31;
  const int bn   = blockIdx.x * TN;
  const int bm   = blockIdx.y * TM;
  const int wr   = wid & 1;    // 0..1 : 64 rows each
  const int wc   = wid >> 1;   // 0..7 : 32 cols each

  const uint32_t smem = (smem_u32(dynsmem) + 1023u) & ~1023u;

  if (tid < TN) sBias[tid] = bias[bn + tid];

  // stage loader: rows are 128B, XOR swizzle on 16B chunks.
  const int lr = tid >> 3;  // 0..63
  const int lc = tid & 7;
  const uint32_t sw = (uint32_t)((lc ^ (lr & 7)) << 4);
  const __half* Ap = g_A;
  const __half* Wp = g_W;

  auto load_stage = [&](int s, int ck) {
    const uint32_t base = smem + (uint32_t)s * STAGE_BYTES;
    const size_t kcol = (size_t)ck * CK + (size_t)lc * 8;
#pragma unroll
    for (int q = 0; q < 2; ++q) {
      const int r = lr + 64 * q;
      const uint32_t doff = (uint32_t)r * 128u + sw;
      cp16(base + doff, Ap + (size_t)(bm + r) * K + kcol);
    }
    const uint32_t wb = base + A_T;
#pragma unroll
    for (int q = 0; q < 4; ++q) {
      const int r = lr + 64 * q;
      const uint32_t doff = (uint32_t)r * 128u + sw;
      cp16(wb + doff, Wp + (size_t)(bn + r) * K + kcol);
    }
    asm volatile("cp.async.commit_group;" ::: "memory");
  };

  // ldmatrix per-lane addressing (verbatim from the passing round-13 kernel).
  const int aRow = wr * 64 + (lane & 15);
  const int aChk = lane >> 4;
  const uint32_t aSwz = (uint32_t)(lane & 7) << 4;
  const int bRow0 = wc * 32 + ((lane >> 4) << 3) + (lane & 7);
  const int bChk = (lane >> 3) & 1;
  const uint32_t bSwz = (uint32_t)(lane & 7) << 4;

  float acc[4][4][4];
#pragma unroll
  for (int i = 0; i < 4; ++i)
#pragma unroll
    for (int j = 0; j < 4; ++j)
#pragma unroll
      for (int t = 0; t < 4; ++t) acc[i][j][t] = 0.0f;

  const int nch = K / CK;
  load_stage(0, 0);

  for (int c = 0; c < nch; ++c) {
    const int s = c & 1;
    if (c + 1 < nch) {
      load_stage(s ^ 1, c + 1);
      asm volatile("cp.async.wait_group 1;" ::: "memory");
    } else {
      asm volatile("cp.async.wait_group 0;" ::: "memory");
    }
    __syncthreads();

    const uint32_t aB = smem + (uint32_t)s * STAGE_BYTES;
    const uint32_t wB = aB + A_T;

#pragma unroll
    for (int ks = 0; ks < 4; ++ks) {
      const uint32_t aOffC = ((uint32_t)((2 * ks + aChk) << 4)) ^ aSwz;
      const uint32_t bOffC = ((uint32_t)((2 * ks + bChk) << 4)) ^ bSwz;

      uint32_t wh[4][2];
#pragma unroll
      for (int jp = 0; jp < 2; ++jp) {
        const uint32_t off = (uint32_t)(bRow0 + jp * 16) * 128u + bOffC;
        ldsm_x4(&wh[2 * jp][0], wB + off);
      }
      uint32_t af[4][4];
#pragma unroll
      for (int i = 0; i < 4; ++i) {
        const uint32_t off = (uint32_t)(aRow + i * 16) * 128u + aOffC;
        ldsm_x4(af[i], aB + off);
      }
#pragma unroll
      for (int i = 0; i < 4; ++i)
#pragma unroll
        for (int j = 0; j < 4; ++j) mma_f16(acc[i][j], af[i], wh[j]);
    }
    __syncthreads();
  }

  // epilogue: bias + tanh + exact JAX noise
  const int r0 = bm + wr * 64 + (lane >> 2);
  const int c0l = wc * 32 + 2 * (lane & 3);
#pragma unroll
  for (int i = 0; i < 4; ++i) {
#pragma unroll
    for (int j = 0; j < 4; ++j) {
      const int cc = c0l + j * 8;
      const int cg = bn + cc;
#pragma unroll
      for (int hrow = 0; hrow < 2; ++hrow) {
        const int m = r0 + i * 16 + hrow * 8;
        const uint32_t nb = (uint32_t)m * 2048u + (uint32_t)cg;
        float v0 = acc[i][j][2 * hrow]     + sBias[cc];
        float v1 = acc[i][j][2 * hrow + 1] + sBias[cc + 1];
        v0 = tanhf(v0) + jax_normal(nk0, nk1, nb)     * 0.02f;
        v1 = tanhf(v1) + jax_normal(nk0, nk1, nb + 1) * 0.02f;
        *reinterpret_cast<float2*>(g_bufB + (size_t)m * HDIM + cg) =
            make_float2(v0, v1);
      }
    }
  }
}

// ---------------------------------------------------------------------------
// colsum two-phase (deterministic) — unchanged.
// ---------------------------------------------------------------------------
__global__ void colsum_part_kernel() {
  const int b = blockIdx.x;
  const int t = threadIdx.x;
  const float* base = g_bufB + (size_t)b * 16 * HDIM;
#pragma unroll
  for (int p = 0; p < 8; ++p) {
    const int c = t + 256 * p;
    float s = 0.0f;
#pragma unroll
    for (int r = 0; r < 16; ++r) s += fabsf(base[(size_t)r * HDIM + c]);
    g_part[b * HDIM + c] = s;
  }
}

__global__ void colsum_reduce_kernel() {
  const int c = blockIdx.x * 256 + threadIdx.x;
  float s = 0.0f;
  for (int p = 0; p < 512; ++p) s += g_part[p * HDIM + c];
  g_cs[c] = s;
}

// ---------------------------------------------------------------------------
// thermal EMA (ping-pong) fused with the crosstalk matvec — unchanged.
// ---------------------------------------------------------------------------
__global__ void thermal_matvec_kernel(int cur, int first) {
  __shared__ float th[HDIM];
  __shared__ float rec[HDIM];
  const int tid = threadIdx.x;  // 128
  const int prev = cur ^ 1;
  for (int i = tid; i < HDIM; i += 128) {
    float lt = g_cs[i] * 0.05f;
    float tv = first ? (0.3f * lt) : (0.7f * g_thermal2[prev][i] + 0.3f * lt);
    th[i] = tv;
    if (blockIdx.x == 0) g_thermal2[cur][i] = tv;
    float d = (float)i;
    rec[i] = (i == 0) ? 0.0f : (1.0f / (d * d));
  }
  __syncthreads();
  const int j = blockIdx.x * 128 + tid;
  float acc = 0.0f;
  for (int i = 0; i < HDIM; ++i) {
    int d = i - j; d = d < 0 ? -d : d;
    acc += th[i] * rec[d];
  }
  g_tn[j] = acc * 0.05f;
}

// colAdd[n] = b[n] + sum_h tn[h]*W[n,h]  (exact fp32 thermal-offset folding).
__global__ void tnw_kernel(const float* __restrict__ W,
                           const float* __restrict__ b) {
  const int wid = threadIdx.x >> 5;
  const int lane = threadIdx.x & 31;
  const int n = blockIdx.x * 8 + wid;
  const float* row = W + (size_t)n * HDIM;
  float s = 0.0f;
  for (int h = lane; h < HDIM; h += 32) s += g_tn[h] * row[h];
#pragma unroll
  for (int o = 16; o > 0; o >>= 1) s += __shfl_xor_sync(0xFFFFFFFFu, s, o);
  if (lane == 0) g_colAdd[n] = s + b[n];
}

// ---------------------------------------------------------------------------
// finalize (layer 0): z = y + tn; phase noise; (x - tn) -> single fp16 A.
// ---------------------------------------------------------------------------
__global__ void finalize_kernel(uint32_t kp0, uint32_t kp1) {
  const int gi = blockIdx.x * blockDim.x + threadIdx.x;
  const int idx = gi << 2;
  float4 y = *reinterpret_cast<const float4*>(g_bufB + idx);
  float4 t = *reinterpret_cast<const float4*>(g_tn + (idx & 2047));
  float v[4] = {y.x, y.y, y.z, y.w};
  float tv[4] = {t.x, t.y, t.z, t.w};
  __half h[4];
#pragma unroll
  for (int c = 0; c < 4; ++c) {
    float z = v[c] + tv[c];
    float ph = jax_normal(kp0, kp1, (uint32_t)(idx + c)) * 0.03f;
    float xx = z + (z * cosf(ph) - z) * 0.03f;
    h[c] = __float2half_rn(xx - tv[c]);
  }
  __half2* A = reinterpret_cast<__half2*>(g_A);
  A[2 * gi]     = __halves2half2(h[0], h[1]);
  A[2 * gi + 1] = __halves2half2(h[2], h[3]);
}

// ---------------------------------------------------------------------------
// finalize (layer 1) fused with output GEMM (D_out=2) — unchanged.
// ---------------------------------------------------------------------------
__global__ void __launch_bounds__(256)
finalize_out_kernel(const float* __restrict__ Wout,
                    const float* __restrict__ bout,
                    float* __restrict__ out,
                    uint32_t kp0, uint32_t kp1) {
  const int b = blockIdx.x;
  const int tid = threadIdx.x;
  const float* row = g_bufB + (size_t)b * 2048;
  float a0 = 0.0f, a1 = 0.0f;
#pragma unroll
  for (int q = 0; q < 2; ++q) {
    const int h = (tid + q * 256) * 4;
    float4 y  = *reinterpret_cast<const float4*>(row + h);
    float4 t  = *reinterpret_cast<const float4*>(g_tn + h);
    float4 w0 = *reinterpret_cast<const float4*>(Wout + h);
    float4 w1 = *reinterpret_cast<const float4*>(Wout + 2048 + h);
    float yv[4] = {y.x, y.y, y.z, y.w};
    float tv[4] = {t.x, t.y, t.z, t.w};
    float w0v[4] = {w0.x, w0.y, w0.z, w0.w};
    float w1v[4] = {w1.x, w1.y, w1.z, w1.w};
#pragma unroll
    for (int c = 0; c < 4; ++c) {
      float xx = yv[c] + tv[c];
      float ph = jax_normal(kp0, kp1, (uint32_t)(b * 2048 + h + c)) * 0.03f;
      xx = xx + (xx * cosf(ph) - xx) * 0.03f;
      a0 += xx * w0v[c];
      a1 += xx * w1v[c];
    }
  }
  __shared__ float s0[256];
  __shared__ float s1[256];
  s0[tid] = a0; s1[tid] = a1;
  __syncthreads();
#pragma unroll
  for (int off = 128; off > 0; off >>= 1) {
    if (tid < off) { s0[tid] += s0[tid + off]; s1[tid] += s1[tid + off]; }
    __syncthreads();
  }
  if (tid == 0) {
    out[2 * b + 0] = s0[0] + bout[0];
    out[2 * b + 1] = s1[0] + bout[1];
  }
}

// ---------------------------------------------------------------------------
// Launch
// ---------------------------------------------------------------------------
extern "C" void kernel_launch(void* const* d_in, const int* in_sizes, int n_in,
                              void* d_out, int out_size) {
  (void)in_sizes; (void)n_in; (void)out_size;
  const float* x    = (const float*)d_in[0];
  const float* W1   = (const float*)d_in[1];
  const float* b1   = (const float*)d_in[2];
  const float* W2   = (const float*)d_in[3];
  const float* b2   = (const float*)d_in[4];
  const float* Wout = (const float*)d_in[5];
  const float* bout = (const float*)d_in[6];
  float* out = (float*)d_out;

  cudaFuncSetAttribute(gemm_fp16_kernel,
                       cudaFuncAttributeMaxDynamicSharedMemorySize,
                       GEMM_DYN_SMEM);

  // Device address of g_colAdd (host-side __device__ symbol use is UB).
  float* colAddPtr = nullptr;
  cudaGetSymbolAddress((void**)&colAddPtr, g_colAdd);

  uint32_t kno[2][2], kph[2][2];
  for (int li = 0; li < 2; ++li) {
    threefry2x32(0u, 42u, 0u, (uint32_t)(2 * li),     kno[li][0], kno[li][1]);
    threefry2x32(0u, 42u, 0u, (uint32_t)(2 * li + 1), kph[li][0], kph[li][1]);
  }

  const dim3 ggrid(HDIM / TN, BATCH / TM);  // 8 x 64

  // Layer 0 (K = 1024); bias = b1 (no thermal offset yet).
  convert_w_kernel<<<2048, 256>>>(W1, 2048 * 1024 / 4);
  tanh_in_kernel<<<8192, 256>>>(x);
  gemm_fp16_kernel<<<ggrid, 512, GEMM_DYN_SMEM>>>(b1, 1024,
                                                  kno[0][0], kno[0][1]);
  colsum_part_kernel<<<512, 256>>>();
  colsum_reduce_kernel<<<8, 256>>>();
  thermal_matvec_kernel<<<16, 128>>>(0, 1);
  tnw_kernel<<<256, 256>>>(W2, b2);
  finalize_kernel<<<16384, 256>>>(kph[0][0], kph[0][1]);

  // Layer 1 (K = 2048); bias = b2 + tn@W2^T (exact fp32), A offset-free.
  convert_w_kernel<<<4096, 256>>>(W2, 2048 * 2048 / 4);
  gemm_fp16_kernel<<<ggrid, 512, GEMM_DYN_SMEM>>>(colAddPtr, 2048,
                                                  kno[1][0], kno[1][1]);
  colsum_part_kernel<<<512, 256>>>();
  colsum_reduce_kernel<<<8, 256>>>();
  thermal_matvec_kernel<<<16, 128>>>(1, 0);

  finalize_out_kernel<<<8192, 256>>>(Wout, bout, out, kph[1][0], kph[1][1]);
}